// round 9
// baseline (speedup 1.0000x reference)
#include <cuda_runtime.h>
#include <cuda_bf16.h>
#include <cstdint>

// ---------------------------------------------------------------------------
// Round 9: cluster-of-8 LSTM. Batch group = CUDA cluster (8 slice-CTAs).
// h is PUSHED over DSMEM (st.shared::cluster) into every peer's double-
// buffered A_h smem region; arrival signaled via mbarrier (count=8,
// release/acquire cluster scope). No global h traffic, no global barrier.
// Math unchanged from round 8: 3-pass bf16-split mma.sync, B_hi in regs.
// ---------------------------------------------------------------------------

#define SEQ     512
#define BATCH   512
#define INPUT   128
#define HIDDEN  256
#define NCTA    128
#define NTHR    256
#define MR      32
#define NC      128
#define KTOT    384
#define CLUSTER 8

// smem layout (bytes)
#define BPITCH  784
#define XPITCH  272
#define HPITCH  528
#define GPITCH  136          // floats
#define BLO_O   0            // 128*784 = 100352
#define AX_O    100352       // x hi: 2 bufs x 8704
#define AXL_O   117760       // x lo: 2 bufs x 8704
#define AH_O    135168       // h: 2 bufs x (hi 16896 + lo 16896) = 67584
#define HBUF    33792
#define HLOFF   16896
#define GSM_O   202752       // 32*136*4 = 17408
#define MBAR_O  220160       // 2 mbarriers
#define SMEM_BYTES 220192
#define XBUF    8704

__device__ __align__(16) __nv_bfloat16 g_xhi[SEQ * BATCH * INPUT];
__device__ __align__(16) __nv_bfloat16 g_xlo[SEQ * BATCH * INPUT];

// ---------------------------------------------------------------------------
__device__ __forceinline__ uint32_t smem_u32(const void* p) {
    uint32_t a;
    asm("{ .reg .u64 t; cvta.to.shared.u64 t, %1; cvt.u32.u64 %0, t; }"
        : "=r"(a) : "l"(p));
    return a;
}
__device__ __forceinline__ void ldsm4(uint32_t* r, uint32_t addr) {
    asm volatile("ldmatrix.sync.aligned.m8n8.x4.shared.b16 {%0,%1,%2,%3}, [%4];"
        : "=r"(r[0]), "=r"(r[1]), "=r"(r[2]), "=r"(r[3]) : "r"(addr));
}
__device__ __forceinline__ void ldsm2(uint32_t* r, uint32_t addr) {
    asm volatile("ldmatrix.sync.aligned.m8n8.x2.shared.b16 {%0,%1}, [%2];"
        : "=r"(r[0]), "=r"(r[1]) : "r"(addr));
}
__device__ __forceinline__ void mma_bf16(float* d, const uint32_t* a,
                                         const uint32_t* b) {
    asm volatile("mma.sync.aligned.m16n8k16.row.col.f32.bf16.bf16.f32 "
        "{%0,%1,%2,%3}, {%4,%5,%6,%7}, {%8,%9}, {%0,%1,%2,%3};"
        : "+f"(d[0]), "+f"(d[1]), "+f"(d[2]), "+f"(d[3])
        : "r"(a[0]), "r"(a[1]), "r"(a[2]), "r"(a[3]), "r"(b[0]), "r"(b[1]));
}
__device__ __forceinline__ void cpasync16(uint32_t dst, const void* src) {
    asm volatile("cp.async.cg.shared.global [%0], [%1], 16;"
        :: "r"(dst), "l"(src));
}
#define CP_COMMIT() asm volatile("cp.async.commit_group;" ::: "memory")
#define CP_WAIT0()  asm volatile("cp.async.wait_group 0;" ::: "memory")

#define CLUSTER_SYNC() do { \
    asm volatile("barrier.cluster.arrive.aligned;" ::: "memory"); \
    asm volatile("barrier.cluster.wait.aligned;" ::: "memory"); \
} while (0)
#define MB_INIT(mb, n) \
    asm volatile("mbarrier.init.shared.b64 [%0], %1;" \
                 :: "r"((uint32_t)(mb)), "r"((uint32_t)(n)) : "memory")
#define MBAR_ARRIVE_RANK(laddr, r) \
    asm volatile("{ .reg .b32 ra; mapa.shared::cluster.u32 ra, %0, %1; " \
        "mbarrier.arrive.release.cluster.shared::cluster.b64 _, [ra]; }" \
        :: "r"((uint32_t)(laddr)), "r"((uint32_t)(r)) : "memory")
#define MB_WAIT_CLUSTER(mb, ph) do {                                          \
    uint32_t _m = (uint32_t)(mb), _p = (uint32_t)(ph), _d;                    \
    asm volatile("{ .reg .pred p; "                                           \
        "mbarrier.try_wait.parity.acquire.cluster.shared::cta.b64 p, [%1], %2; " \
        "selp.b32 %0, 1, 0, p; }" : "=r"(_d) : "r"(_m), "r"(_p) : "memory");  \
    if (!_d) {                                                                \
        asm volatile("{ .reg .pred P1; WL_%=: "                               \
            "mbarrier.try_wait.parity.acquire.cluster.shared::cta.b64 P1, [%0], %1, 0x989680; " \
            "@P1 bra.uni WD_%=; bra.uni WL_%=; WD_%=: }"                      \
            :: "r"(_m), "r"(_p) : "memory");                                  \
    }                                                                         \
} while (0)
__device__ __forceinline__ uint32_t mapa_rank(uint32_t laddr, uint32_t r) {
    uint32_t ra;
    asm("mapa.shared::cluster.u32 %0, %1, %2;" : "=r"(ra) : "r"(laddr), "r"(r));
    return ra;
}
__device__ __forceinline__ void st_cluster64(uint32_t addr, unsigned long long v) {
    asm volatile("st.shared::cluster.b64 [%0], %1;" :: "r"(addr), "l"(v) : "memory");
}

__device__ __forceinline__ float sigf(float v)  { return 1.0f / (1.0f + __expf(-v)); }
__device__ __forceinline__ float tanhx(float v) { return 2.0f / (1.0f + __expf(-2.0f * v)) - 1.0f; }
__device__ __forceinline__ uint32_t pk2(float a, float b) {
    __nv_bfloat162 t = __floats2bfloat162_rn(a, b);
    return *reinterpret_cast<uint32_t*>(&t);
}

// ---------------------------------------------------------------------------
__global__ void prep_x(const float* __restrict__ x) {
    const int N4 = SEQ * BATCH * INPUT / 4;
    for (int i = blockIdx.x * blockDim.x + threadIdx.x; i < N4;
         i += gridDim.x * blockDim.x) {
        float4 v = *reinterpret_cast<const float4*>(x + 4 * i);
        float hx = __bfloat162float(__float2bfloat16(v.x));
        float hy = __bfloat162float(__float2bfloat16(v.y));
        float hz = __bfloat162float(__float2bfloat16(v.z));
        float hw = __bfloat162float(__float2bfloat16(v.w));
        uint2 hi, lo;
        hi.x = pk2(v.x, v.y); hi.y = pk2(v.z, v.w);
        lo.x = pk2(v.x - hx, v.y - hy); lo.y = pk2(v.z - hz, v.w - hw);
        reinterpret_cast<uint2*>(g_xhi)[i] = hi;
        reinterpret_cast<uint2*>(g_xlo)[i] = lo;
    }
}

// ---------------------------------------------------------------------------
__global__ void __launch_bounds__(NTHR, 1)
lstm_mma(const float* __restrict__ W_ih, const float* __restrict__ W_hh,
         const float* __restrict__ b_ih, const float* __restrict__ b_hh,
         const float* __restrict__ W_out, const float* __restrict__ b_out,
         float* __restrict__ out) {
    extern __shared__ char smem[];
    const uint32_t sA = smem_u32(smem);
    float* gsmf = reinterpret_cast<float*>(smem + GSM_O);

    const int tid  = threadIdx.x;
    const int wid  = tid >> 5;
    const int lane = tid & 31;
    const int g     = blockIdx.x >> 3;    // batch group == cluster id
    const int slice = blockIdx.x & 7;     // == cluster rank
    const int nq = wid;
    const int l15 = lane & 31 & 15;

    // ---- mbarrier init (count = 8 arrivals, one per cluster CTA) ----
    if (tid == 0) {
        MB_INIT(sA + MBAR_O + 0, CLUSTER);
        MB_INIT(sA + MBAR_O + 8, CLUSTER);
    }

    // ---- build B_lo in smem ----
    for (int i = tid; i < NC * KTOT; i += NTHR) {
        int n = i / KTOT, k = i - n * KTOT;
        int gcol = (n >> 5) * HIDDEN + slice * 32 + (n & 31);
        float wv = (k < INPUT) ? W_ih[(size_t)gcol * INPUT + k]
                               : W_hh[(size_t)gcol * HIDDEN + (k - INPUT)];
        __nv_bfloat16 bhv = __float2bfloat16(wv);
        __nv_bfloat16 blv = __float2bfloat16(wv - __bfloat162float(bhv));
        *reinterpret_cast<__nv_bfloat16*>(smem + BLO_O + n * BPITCH + 2 * k) = blv;
    }

    // ---- B_hi -> regs, staged in 2 phases of 64 cols (aliased at AX_O) ----
    uint32_t bh[24][2][2];
    #pragma unroll
    for (int p = 0; p < 2; ++p) {
        __syncthreads();
        for (int i = tid; i < 64 * KTOT; i += NTHR) {
            int n = i / KTOT, k = i - n * KTOT;
            int gn = p * 64 + n;
            int gcol = (gn >> 5) * HIDDEN + slice * 32 + (gn & 31);
            float wv = (k < INPUT) ? W_ih[(size_t)gcol * INPUT + k]
                                   : W_hh[(size_t)gcol * HIDDEN + (k - INPUT)];
            *reinterpret_cast<__nv_bfloat16*>(smem + AX_O + n * BPITCH + 2 * k) =
                __float2bfloat16(wv);
        }
        __syncthreads();
        if ((nq >> 2) == p) {
            int nloc = 16 * (nq & 3);
            uint32_t base = sA + AX_O + (uint32_t)(nloc + (l15 & 7)) * BPITCH
                          + (uint32_t)((l15 >> 3) & 1) * 16;
            #pragma unroll
            for (int kt = 0; kt < 24; ++kt) {
                ldsm2(&bh[kt][0][0], base + kt * 32);
                ldsm2(&bh[kt][1][0], base + 8 * BPITCH + kt * 32);
            }
        }
    }
    __syncthreads();

    // ---- zero A_h buffer 1 (read at s=0) ----
    for (int i = tid; i < HBUF / 4; i += NTHR)
        reinterpret_cast<uint32_t*>(smem + AH_O + HBUF)[i] = 0;

    // ---- stage x[0] into x-buffer 0 ----
    {
        const __nv_bfloat16* xh_ = g_xhi + (size_t)(g * MR) * INPUT;
        const __nv_bfloat16* xl_ = g_xlo + (size_t)(g * MR) * INPUT;
        for (int i = tid; i < MR * 16; i += NTHR) {
            int r = i >> 4, ch = i & 15;
            uint32_t dst = sA + AX_O + r * XPITCH + ch * 16;
            cpasync16(dst, xh_ + r * INPUT + ch * 8);
            cpasync16(dst + (AXL_O - AX_O), xl_ + r * INPUT + ch * 8);
        }
        CP_COMMIT();
        CP_WAIT0();
    }
    __syncthreads();
    CLUSTER_SYNC();   // mbarriers inited everywhere before any arrive

    // ---- per-lane ldmatrix bases ----
    const uint32_t baseX  = sA + AX_O + (uint32_t)l15 * XPITCH
                          + (uint32_t)(lane >> 4) * 16;
    const uint32_t baseH0 = sA + AH_O + (uint32_t)l15 * HPITCH
                          + (uint32_t)(lane >> 4) * 16;
    const uint32_t baseBL = sA + BLO_O + (uint32_t)(16 * nq + (l15 & 7)) * BPITCH
                          + (uint32_t)((l15 >> 3) & 1) * 16;

    // ---- bias C init ----
    float cb[2][2];
    #pragma unroll
    for (int nt = 0; nt < 2; ++nt) {
        int c0 = 16 * nq + 8 * nt + 2 * (lane & 3);
        int gc0 = (c0 >> 5) * HIDDEN + slice * 32 + (c0 & 31);
        int c1 = c0 + 1;
        int gc1 = (c1 >> 5) * HIDDEN + slice * 32 + (c1 & 31);
        cb[nt][0] = b_ih[gc0] + b_hh[gc0];
        cb[nt][1] = b_ih[gc1] + b_hh[gc1];
    }

    // ---- epilogue ownership + precomputed DSMEM dst bases (8 ranks) ----
    const int er = tid >> 3;
    const int u0 = (tid & 7) << 2;
    const uint32_t lhbase = sA + AH_O + (uint32_t)er * HPITCH
                          + (uint32_t)(slice * 32 + u0) * 2;
    uint32_t dsth[CLUSTER];
    #pragma unroll
    for (int r = 0; r < CLUSTER; ++r) dsth[r] = mapa_rank(lhbase, r);

    float cst[4] = {0.f, 0.f, 0.f, 0.f};
    int ph0 = 0, ph1 = 0;

    for (int s = 0; s < SEQ; ++s) {
        const int bw = s & 1;              // write buffer for h(s)
        const int br = bw ^ 1;             // read buffer (h(s-1))

        // ===== prefetch x(s+1) =====
        if (s + 1 < SEQ) {
            const __nv_bfloat16* xh_ = g_xhi + ((size_t)(s + 1) * BATCH + g * MR) * INPUT;
            const __nv_bfloat16* xl_ = g_xlo + ((size_t)(s + 1) * BATCH + g * MR) * INPUT;
            uint32_t xb = ((s + 1) & 1) * XBUF;
            for (int i = tid; i < MR * 16; i += NTHR) {
                int r = i >> 4, ch = i & 15;
                uint32_t dst = sA + AX_O + xb + r * XPITCH + ch * 16;
                cpasync16(dst, xh_ + r * INPUT + ch * 8);
                cpasync16(dst + (AXL_O - AX_O), xl_ + r * INPUT + ch * 8);
            }
        }
        CP_COMMIT();

        // ===== x-part MMAs (kt 0..7) — covers peer skew + DSMEM drain =====
        float d[2][2][4];
        #pragma unroll
        for (int mt = 0; mt < 2; ++mt)
            #pragma unroll
            for (int nt = 0; nt < 2; ++nt) {
                d[mt][nt][0] = cb[nt][0]; d[mt][nt][1] = cb[nt][1];
                d[mt][nt][2] = cb[nt][0]; d[mt][nt][3] = cb[nt][1];
            }
        {
            uint32_t bx = baseX + bw * XBUF;
            #pragma unroll
            for (int kt = 0; kt < 8; ++kt) {
                uint32_t ah0[4], ah1[4], al0[4], al1[4], bl0[2], bl1[2];
                ldsm4(ah0, bx + kt * 32);
                ldsm4(ah1, bx + 16 * XPITCH + kt * 32);
                ldsm4(al0, bx + (AXL_O - AX_O) + kt * 32);
                ldsm4(al1, bx + (AXL_O - AX_O) + 16 * XPITCH + kt * 32);
                ldsm2(bl0, baseBL + kt * 32);
                ldsm2(bl1, baseBL + 8 * BPITCH + kt * 32);
                mma_bf16(d[0][0], ah0, bh[kt][0]); mma_bf16(d[0][1], ah0, bh[kt][1]);
                mma_bf16(d[1][0], ah1, bh[kt][0]); mma_bf16(d[1][1], ah1, bh[kt][1]);
                mma_bf16(d[0][0], al0, bh[kt][0]); mma_bf16(d[0][1], al0, bh[kt][1]);
                mma_bf16(d[1][0], al1, bh[kt][0]); mma_bf16(d[1][1], al1, bh[kt][1]);
                mma_bf16(d[0][0], ah0, bl0); mma_bf16(d[0][1], ah0, bl1);
                mma_bf16(d[1][0], ah1, bl0); mma_bf16(d[1][1], ah1, bl1);
            }
        }

        // ===== wait for h(s-1) arrivals (mbar[br]) =====
        if (s > 0) {
            uint32_t mb = sA + MBAR_O + br * 8;
            if (br == 0) { MB_WAIT_CLUSTER(mb, ph0); ph0 ^= 1; }
            else         { MB_WAIT_CLUSTER(mb, ph1); ph1 ^= 1; }
        }

        // ===== h-part MMAs (kt 8..23) from A_h[br] =====
        {
            uint32_t bhm = baseH0 + br * HBUF;
            #pragma unroll
            for (int kt = 8; kt < 24; ++kt) {
                uint32_t ah0[4], ah1[4], al0[4], al1[4], bl0[2], bl1[2];
                uint32_t ko = (kt - 8) * 32;
                ldsm4(ah0, bhm + ko);
                ldsm4(ah1, bhm + 16 * HPITCH + ko);
                ldsm4(al0, bhm + HLOFF + ko);
                ldsm4(al1, bhm + HLOFF + 16 * HPITCH + ko);
                ldsm2(bl0, baseBL + kt * 32);
                ldsm2(bl1, baseBL + 8 * BPITCH + kt * 32);
                mma_bf16(d[0][0], ah0, bh[kt][0]); mma_bf16(d[0][1], ah0, bh[kt][1]);
                mma_bf16(d[1][0], ah1, bh[kt][0]); mma_bf16(d[1][1], ah1, bh[kt][1]);
                mma_bf16(d[0][0], al0, bh[kt][0]); mma_bf16(d[0][1], al0, bh[kt][1]);
                mma_bf16(d[1][0], al1, bh[kt][0]); mma_bf16(d[1][1], al1, bh[kt][1]);
                mma_bf16(d[0][0], ah0, bl0); mma_bf16(d[0][1], ah0, bl1);
                mma_bf16(d[1][0], ah1, bl0); mma_bf16(d[1][1], ah1, bl1);
            }
        }

        // ===== fragments -> gsm; drain x prefetch =====
        #pragma unroll
        for (int mt = 0; mt < 2; ++mt)
            #pragma unroll
            for (int nt = 0; nt < 2; ++nt) {
                int r0 = 16 * mt + (lane >> 2);
                int c0 = 16 * nq + 8 * nt + 2 * (lane & 3);
                *reinterpret_cast<float2*>(&gsmf[r0 * GPITCH + c0]) =
                    make_float2(d[mt][nt][0], d[mt][nt][1]);
                *reinterpret_cast<float2*>(&gsmf[(r0 + 8) * GPITCH + c0]) =
                    make_float2(d[mt][nt][2], d[mt][nt][3]);
            }
        CP_WAIT0();
        __syncthreads();

        // ===== epilogue: cell update + DSMEM push of h(s) to all 8 ranks ====
        {
            float4 gi = *reinterpret_cast<const float4*>(&gsmf[er * GPITCH +  0 + u0]);
            float4 gf = *reinterpret_cast<const float4*>(&gsmf[er * GPITCH + 32 + u0]);
            float4 gg = *reinterpret_cast<const float4*>(&gsmf[er * GPITCH + 64 + u0]);
            float4 go = *reinterpret_cast<const float4*>(&gsmf[er * GPITCH + 96 + u0]);
            float hn[4];
            cst[0] = sigf(gf.x) * cst[0] + sigf(gi.x) * tanhx(gg.x);
            cst[1] = sigf(gf.y) * cst[1] + sigf(gi.y) * tanhx(gg.y);
            cst[2] = sigf(gf.z) * cst[2] + sigf(gi.z) * tanhx(gg.z);
            cst[3] = sigf(gf.w) * cst[3] + sigf(gi.w) * tanhx(gg.w);
            hn[0] = sigf(go.x) * tanhx(cst[0]);
            hn[1] = sigf(go.y) * tanhx(cst[1]);
            hn[2] = sigf(go.z) * tanhx(cst[2]);
            hn[3] = sigf(go.w) * tanhx(cst[3]);
            float h0 = __bfloat162float(__float2bfloat16(hn[0]));
            float h1 = __bfloat162float(__float2bfloat16(hn[1]));
            float h2 = __bfloat162float(__float2bfloat16(hn[2]));
            float h3 = __bfloat162float(__float2bfloat16(hn[3]));
            unsigned long long hv64 =
                ((unsigned long long)(uint32_t)pk2(hn[2], hn[3]) << 32) |
                (uint32_t)pk2(hn[0], hn[1]);
            unsigned long long lv64 =
                ((unsigned long long)(uint32_t)pk2(hn[2] - h2, hn[3] - h3) << 32) |
                (uint32_t)pk2(hn[0] - h0, hn[1] - h1);
            uint32_t bo = (uint32_t)bw * HBUF;
            #pragma unroll
            for (int r = 0; r < CLUSTER; ++r) {
                st_cluster64(dsth[r] + bo, hv64);
                st_cluster64(dsth[r] + bo + HLOFF, lv64);
            }
        }
        __syncthreads();

        // ===== signal: arrive on every rank's mbar[bw] =====
        if (tid < CLUSTER) {
            asm volatile("fence.acq_rel.cluster;" ::: "memory");
            MBAR_ARRIVE_RANK(sA + MBAR_O + bw * 8, tid);
        }
    }

    // ---- final projection (rank 0): h(511) is in own smem A_h buf 1 ----
    if (slice == 0) {
        MB_WAIT_CLUSTER(sA + MBAR_O + 8, ph1);   // h(511) -> buf 1
        const char* hb = smem + AH_O + HBUF;     // hi plane
        const float bo = b_out[0];
        for (int r4 = 0; r4 < 4; ++r4) {
            int r = wid * 4 + r4;
            float acc = 0.0f;
            #pragma unroll
            for (int q = 0; q < 8; ++q) {
                int c = lane * 8 + q;
                float hv = __bfloat162float(
                    *reinterpret_cast<const __nv_bfloat16*>(hb + r * HPITCH + 2 * c));
                float lv = __bfloat162float(
                    *reinterpret_cast<const __nv_bfloat16*>(hb + HLOFF + r * HPITCH + 2 * c));
                acc += (hv + lv) * W_out[c];
            }
            #pragma unroll
            for (int off = 16; off > 0; off >>= 1)
                acc += __shfl_xor_sync(0xFFFFFFFFu, acc, off);
            if (lane == 0) out[g * MR + r] = acc + bo;
        }
    }
    CLUSTER_SYNC();   // no CTA exits while peers may still push into it
}

// ---------------------------------------------------------------------------
extern "C" void kernel_launch(void* const* d_in, const int* in_sizes, int n_in,
                              void* d_out, int out_size) {
    const float* x     = (const float*)d_in[0];
    const float* W_ih  = (const float*)d_in[1];
    const float* W_hh  = (const float*)d_in[2];
    const float* b_ih  = (const float*)d_in[3];
    const float* b_hh  = (const float*)d_in[4];
    const float* W_out = (const float*)d_in[5];
    const float* b_out = (const float*)d_in[6];
    float* out = (float*)d_out;

    prep_x<<<2048, 256>>>(x);

    cudaFuncSetAttribute(lstm_mma,
                         cudaFuncAttributeMaxDynamicSharedMemorySize, SMEM_BYTES);
    cudaLaunchConfig_t cfg = {};
    cfg.gridDim = dim3(NCTA, 1, 1);
    cfg.blockDim = dim3(NTHR, 1, 1);
    cfg.dynamicSmemBytes = SMEM_BYTES;
    cfg.stream = 0;
    cudaLaunchAttribute attrs[1];
    attrs[0].id = cudaLaunchAttributeClusterDimension;
    attrs[0].val.clusterDim.x = CLUSTER;
    attrs[0].val.clusterDim.y = 1;
    attrs[0].val.clusterDim.z = 1;
    cfg.attrs = attrs;
    cfg.numAttrs = 1;
    cudaLaunchKernelEx(&cfg, lstm_mma, W_ih, W_hh, b_ih, b_hh,
                       W_out, b_out, out);
}

// round 10
// speedup vs baseline: 1.5788x; 1.5788x over previous
#include <cuda_runtime.h>
#include <cuda_bf16.h>
#include <cstdint>

// ---------------------------------------------------------------------------
// Round 10: 2 CTAs/SM. 16 batch-groups (M=32) x 16 slices (N=64) = 256 CTAs,
// 128 threads each, smem 110080 B -> 2 co-resident CTAs per SM. One CTA's
// MMA phase hides the other's barrier/copy/HMMA-chain latency.
// Math unchanged: 3-pass bf16-split mma.sync, B_hi register-resident.
// Step order: barrier-wait -> issue h cp.async -> x-MMAs (cover h latency)
// -> sync -> prefetch x(s+1) into single x buffer -> h-MMAs (cover x copy).
// ---------------------------------------------------------------------------

#define SEQ     512
#define BATCH   512
#define INPUT   128
#define HIDDEN  256
#define NGROUP  16
#define NSLICE  16
#define NCTA    256
#define NTHR    128
#define MR      32
#define NC      64
#define KTOT    384

// smem layout (bytes)
#define BPITCH  784
#define XPITCH  272
#define HPITCH  528
#define GPITCH  68           // floats
#define BLO_O   0            // 64*784 = 50176
#define AX_O    50176        // x hi (8704)
#define AXL_O   58880        // x lo (8704)
#define AH_O    67584        // h hi (16896)
#define AHL_O   84480        // h lo (16896)
#define GSM_O   101376       // 32*68*4 = 8704
#define SMEM_BYTES 110080

__device__ __align__(16) __nv_bfloat16 g_xhi[SEQ * BATCH * INPUT];
__device__ __align__(16) __nv_bfloat16 g_xlo[SEQ * BATCH * INPUT];
__device__ __align__(16) __nv_bfloat16 g_hh[2][NGROUP][MR][HIDDEN];
__device__ __align__(16) __nv_bfloat16 g_hl[2][NGROUP][MR][HIDDEN];
__device__ int g_bar_count[NGROUP];
__device__ int g_bar_sense[NGROUP];

// ---------------------------------------------------------------------------
__device__ __forceinline__ uint32_t smem_u32(const void* p) {
    uint32_t a;
    asm("{ .reg .u64 t; cvta.to.shared.u64 t, %1; cvt.u32.u64 %0, t; }"
        : "=r"(a) : "l"(p));
    return a;
}
__device__ __forceinline__ void ldsm4(uint32_t* r, uint32_t addr) {
    asm volatile("ldmatrix.sync.aligned.m8n8.x4.shared.b16 {%0,%1,%2,%3}, [%4];"
        : "=r"(r[0]), "=r"(r[1]), "=r"(r[2]), "=r"(r[3]) : "r"(addr));
}
__device__ __forceinline__ void ldsm2(uint32_t* r, uint32_t addr) {
    asm volatile("ldmatrix.sync.aligned.m8n8.x2.shared.b16 {%0,%1}, [%2];"
        : "=r"(r[0]), "=r"(r[1]) : "r"(addr));
}
__device__ __forceinline__ void mma_bf16(float* d, const uint32_t* a,
                                         const uint32_t* b) {
    asm volatile("mma.sync.aligned.m16n8k16.row.col.f32.bf16.bf16.f32 "
        "{%0,%1,%2,%3}, {%4,%5,%6,%7}, {%8,%9}, {%0,%1,%2,%3};"
        : "+f"(d[0]), "+f"(d[1]), "+f"(d[2]), "+f"(d[3])
        : "r"(a[0]), "r"(a[1]), "r"(a[2]), "r"(a[3]), "r"(b[0]), "r"(b[1]));
}
__device__ __forceinline__ void cpasync16(uint32_t dst, const void* src) {
    asm volatile("cp.async.cg.shared.global [%0], [%1], 16;"
        :: "r"(dst), "l"(src));
}
#define CP_COMMIT() asm volatile("cp.async.commit_group;" ::: "memory")
#define CP_WAIT0()  asm volatile("cp.async.wait_group 0;" ::: "memory")
#define CP_WAIT1()  asm volatile("cp.async.wait_group 1;" ::: "memory")

__device__ __forceinline__ float sigf(float v)  { return 1.0f / (1.0f + __expf(-v)); }
__device__ __forceinline__ float tanhx(float v) { return 2.0f / (1.0f + __expf(-2.0f * v)) - 1.0f; }
__device__ __forceinline__ uint32_t pk2(float a, float b) {
    __nv_bfloat162 t = __floats2bfloat162_rn(a, b);
    return *reinterpret_cast<uint32_t*>(&t);
}

// ---------------------------------------------------------------------------
__global__ void prep_x(const float* __restrict__ x) {
    const int N4 = SEQ * BATCH * INPUT / 4;
    for (int i = blockIdx.x * blockDim.x + threadIdx.x; i < N4;
         i += gridDim.x * blockDim.x) {
        float4 v = *reinterpret_cast<const float4*>(x + 4 * i);
        float hx = __bfloat162float(__float2bfloat16(v.x));
        float hy = __bfloat162float(__float2bfloat16(v.y));
        float hz = __bfloat162float(__float2bfloat16(v.z));
        float hw = __bfloat162float(__float2bfloat16(v.w));
        uint2 hi, lo;
        hi.x = pk2(v.x, v.y); hi.y = pk2(v.z, v.w);
        lo.x = pk2(v.x - hx, v.y - hy); lo.y = pk2(v.z - hz, v.w - hw);
        reinterpret_cast<uint2*>(g_xhi)[i] = hi;
        reinterpret_cast<uint2*>(g_xlo)[i] = lo;
    }
}

// ---------------------------------------------------------------------------
__global__ void __launch_bounds__(NTHR, 2)
lstm_mma(const float* __restrict__ W_ih, const float* __restrict__ W_hh,
         const float* __restrict__ b_ih, const float* __restrict__ b_hh,
         const float* __restrict__ W_out, const float* __restrict__ b_out,
         float* __restrict__ out) {
    extern __shared__ char smem[];
    const uint32_t sA = smem_u32(smem);
    float* gsmf = reinterpret_cast<float*>(smem + GSM_O);

    const int tid  = threadIdx.x;
    const int wid  = tid >> 5;
    const int lane = tid & 31;
    const int g     = blockIdx.x >> 4;    // batch group: rows g*32..
    const int slice = blockIdx.x & 15;    // hidden units slice*16..
    const int nq = wid;                   // warp n-strip: cols 16*nq..
    const int l15 = lane & 15;

    // ---- build B_lo in smem ----
    // CTA col n (0..63): gate=n>>4, unit=n&15 -> gcol = gate*256+slice*16+unit
    for (int i = tid; i < NC * KTOT; i += NTHR) {
        int n = i / KTOT, k = i - n * KTOT;
        int gcol = (n >> 4) * HIDDEN + slice * 16 + (n & 15);
        float wv = (k < INPUT) ? W_ih[(size_t)gcol * INPUT + k]
                               : W_hh[(size_t)gcol * HIDDEN + (k - INPUT)];
        __nv_bfloat16 bhv = __float2bfloat16(wv);
        __nv_bfloat16 blv = __float2bfloat16(wv - __bfloat162float(bhv));
        *reinterpret_cast<__nv_bfloat16*>(smem + BLO_O + n * BPITCH + 2 * k) = blv;
    }

    // ---- B_hi -> registers via scratch aliased over x/h regions ----
    uint32_t bh[24][2][2];
    {
        for (int i = tid; i < NC * KTOT; i += NTHR) {
            int n = i / KTOT, k = i - n * KTOT;
            int gcol = (n >> 4) * HIDDEN + slice * 16 + (n & 15);
            float wv = (k < INPUT) ? W_ih[(size_t)gcol * INPUT + k]
                                   : W_hh[(size_t)gcol * HIDDEN + (k - INPUT)];
            *reinterpret_cast<__nv_bfloat16*>(smem + AX_O + n * BPITCH + 2 * k) =
                __float2bfloat16(wv);
        }
        __syncthreads();
        uint32_t base = sA + AX_O + (uint32_t)(16 * nq + (l15 & 7)) * BPITCH
                      + (uint32_t)((l15 >> 3) & 1) * 16;
        #pragma unroll
        for (int kt = 0; kt < 24; ++kt) {
            ldsm2(&bh[kt][0][0], base + kt * 32);
            ldsm2(&bh[kt][1][0], base + 8 * BPITCH + kt * 32);
        }
        __syncthreads();
    }

    // ---- zero h planes (h=0 for step 0) ----
    for (int i = tid; i < (GSM_O - AH_O) / 4; i += NTHR)
        reinterpret_cast<uint32_t*>(smem + AH_O)[i] = 0;

    // ---- stage x[0] ----
    {
        const __nv_bfloat16* xh_ = g_xhi + (size_t)(g * MR) * INPUT;
        const __nv_bfloat16* xl_ = g_xlo + (size_t)(g * MR) * INPUT;
        for (int i = tid; i < MR * 16; i += NTHR) {
            int r = i >> 4, ch = i & 15;
            uint32_t dst = sA + AX_O + r * XPITCH + ch * 16;
            cpasync16(dst, xh_ + r * INPUT + ch * 8);
            cpasync16(dst + (AXL_O - AX_O), xl_ + r * INPUT + ch * 8);
        }
        CP_COMMIT();
        CP_WAIT0();
    }
    __syncthreads();

    // ---- per-lane ldmatrix bases ----
    const uint32_t baseX  = sA + AX_O + (uint32_t)l15 * XPITCH
                          + (uint32_t)(lane >> 4) * 16;
    const uint32_t baseH  = sA + AH_O + (uint32_t)l15 * HPITCH
                          + (uint32_t)(lane >> 4) * 16;
    const uint32_t baseBL = sA + BLO_O + (uint32_t)(16 * nq + (l15 & 7)) * BPITCH
                          + (uint32_t)((l15 >> 3) & 1) * 16;

    // ---- bias C init ----
    float cb[2][2];
    #pragma unroll
    for (int nt = 0; nt < 2; ++nt) {
        int c0 = 16 * nq + 8 * nt + 2 * (lane & 3);
        int gc0 = (c0 >> 4) * HIDDEN + slice * 16 + (c0 & 15);
        int c1 = c0 + 1;
        int gc1 = (c1 >> 4) * HIDDEN + slice * 16 + (c1 & 15);
        cb[nt][0] = b_ih[gc0] + b_hh[gc0];
        cb[nt][1] = b_ih[gc1] + b_hh[gc1];
    }

    const int er = tid >> 2;           // epilogue row 0..31
    const int u0 = (tid & 3) << 2;     // epilogue unit 0..12
    float cst[4] = {0.f, 0.f, 0.f, 0.f};

    for (int s = 0; s < SEQ; ++s) {
        // ===== P0: group barrier wait for h(s-1) =====
        if (s > 0 && tid == 0) {
            volatile int* sp = &g_bar_sense[g];
            int tgt = s & 1;
            while (*sp != tgt) __nanosleep(32);
            __threadfence();
        }
        __syncthreads();

        // ===== P0.5: issue cp.async h(s-1) [group H] =====
        if (s > 0) {
            const __nv_bfloat16* hh = &g_hh[(s - 1) & 1][g][0][0];
            const __nv_bfloat16* hl = &g_hl[(s - 1) & 1][g][0][0];
            for (int i = tid; i < MR * 32; i += NTHR) {
                int r = i >> 5, ch = i & 31;
                uint32_t dst = sA + AH_O + r * HPITCH + ch * 16;
                cpasync16(dst, hh + r * HIDDEN + ch * 8);
                cpasync16(dst + (AHL_O - AH_O), hl + r * HIDDEN + ch * 8);
            }
        }
        CP_COMMIT();                       // group H

        // ===== P1: x-part MMAs (kt 0..7) — cover the h copy =====
        float d[2][2][4];
        #pragma unroll
        for (int mt = 0; mt < 2; ++mt)
            #pragma unroll
            for (int nt = 0; nt < 2; ++nt) {
                d[mt][nt][0] = cb[nt][0]; d[mt][nt][1] = cb[nt][1];
                d[mt][nt][2] = cb[nt][0]; d[mt][nt][3] = cb[nt][1];
            }
        #pragma unroll
        for (int kt = 0; kt < 8; ++kt) {
            uint32_t ah0[4], ah1[4], al0[4], al1[4], bl0[2], bl1[2];
            ldsm4(ah0, baseX + kt * 32);
            ldsm4(ah1, baseX + 16 * XPITCH + kt * 32);
            ldsm4(al0, baseX + (AXL_O - AX_O) + kt * 32);
            ldsm4(al1, baseX + (AXL_O - AX_O) + 16 * XPITCH + kt * 32);
            ldsm2(bl0, baseBL + kt * 32);
            ldsm2(bl1, baseBL + 8 * BPITCH + kt * 32);
            mma_bf16(d[0][0], ah0, bh[kt][0]); mma_bf16(d[0][1], ah0, bh[kt][1]);
            mma_bf16(d[1][0], ah1, bh[kt][0]); mma_bf16(d[1][1], ah1, bh[kt][1]);
            mma_bf16(d[0][0], al0, bh[kt][0]); mma_bf16(d[0][1], al0, bh[kt][1]);
            mma_bf16(d[1][0], al1, bh[kt][0]); mma_bf16(d[1][1], al1, bh[kt][1]);
            mma_bf16(d[0][0], ah0, bl0); mma_bf16(d[0][1], ah0, bl1);
            mma_bf16(d[1][0], ah1, bl0); mma_bf16(d[1][1], ah1, bl1);
        }

        // ===== P2: sync (x consumed by all warps) =====
        __syncthreads();

        // ===== P2.5: prefetch x(s+1) into the (single) x buffer [group X] ====
        if (s + 1 < SEQ) {
            const __nv_bfloat16* xh_ = g_xhi + ((size_t)(s + 1) * BATCH + g * MR) * INPUT;
            const __nv_bfloat16* xl_ = g_xlo + ((size_t)(s + 1) * BATCH + g * MR) * INPUT;
            for (int i = tid; i < MR * 16; i += NTHR) {
                int r = i >> 4, ch = i & 15;
                uint32_t dst = sA + AX_O + r * XPITCH + ch * 16;
                cpasync16(dst, xh_ + r * INPUT + ch * 8);
                cpasync16(dst + (AXL_O - AX_O), xl_ + r * INPUT + ch * 8);
            }
        }
        CP_COMMIT();                       // group X

        // ===== P3: wait H =====
        CP_WAIT1();
        __syncthreads();

        // ===== P4: h-part MMAs (kt 8..23) — cover the x prefetch =====
        #pragma unroll
        for (int kt = 8; kt < 24; ++kt) {
            uint32_t ah0[4], ah1[4], al0[4], al1[4], bl0[2], bl1[2];
            uint32_t ko = (kt - 8) * 32;
            ldsm4(ah0, baseH + ko);
            ldsm4(ah1, baseH + 16 * HPITCH + ko);
            ldsm4(al0, baseH + (AHL_O - AH_O) + ko);
            ldsm4(al1, baseH + (AHL_O - AH_O) + 16 * HPITCH + ko);
            ldsm2(bl0, baseBL + kt * 32);
            ldsm2(bl1, baseBL + 8 * BPITCH + kt * 32);
            mma_bf16(d[0][0], ah0, bh[kt][0]); mma_bf16(d[0][1], ah0, bh[kt][1]);
            mma_bf16(d[1][0], ah1, bh[kt][0]); mma_bf16(d[1][1], ah1, bh[kt][1]);
            mma_bf16(d[0][0], al0, bh[kt][0]); mma_bf16(d[0][1], al0, bh[kt][1]);
            mma_bf16(d[1][0], al1, bh[kt][0]); mma_bf16(d[1][1], al1, bh[kt][1]);
            mma_bf16(d[0][0], ah0, bl0); mma_bf16(d[0][1], ah0, bl1);
            mma_bf16(d[1][0], ah1, bl0); mma_bf16(d[1][1], ah1, bl1);
        }

        // ===== P5: fragments -> gsm; drain X =====
        #pragma unroll
        for (int mt = 0; mt < 2; ++mt)
            #pragma unroll
            for (int nt = 0; nt < 2; ++nt) {
                int r0 = 16 * mt + (lane >> 2);
                int c0 = 16 * nq + 8 * nt + 2 * (lane & 3);
                *reinterpret_cast<float2*>(&gsmf[r0 * GPITCH + c0]) =
                    make_float2(d[mt][nt][0], d[mt][nt][1]);
                *reinterpret_cast<float2*>(&gsmf[(r0 + 8) * GPITCH + c0]) =
                    make_float2(d[mt][nt][2], d[mt][nt][3]);
            }
        CP_WAIT0();
        __syncthreads();

        // ===== P6: epilogue — cell update + publish h(s) =====
        {
            float4 gi = *reinterpret_cast<const float4*>(&gsmf[er * GPITCH +  0 + u0]);
            float4 gf = *reinterpret_cast<const float4*>(&gsmf[er * GPITCH + 16 + u0]);
            float4 gg = *reinterpret_cast<const float4*>(&gsmf[er * GPITCH + 32 + u0]);
            float4 go = *reinterpret_cast<const float4*>(&gsmf[er * GPITCH + 48 + u0]);
            float hn[4];
            cst[0] = sigf(gf.x) * cst[0] + sigf(gi.x) * tanhx(gg.x);
            cst[1] = sigf(gf.y) * cst[1] + sigf(gi.y) * tanhx(gg.y);
            cst[2] = sigf(gf.z) * cst[2] + sigf(gi.z) * tanhx(gg.z);
            cst[3] = sigf(gf.w) * cst[3] + sigf(gi.w) * tanhx(gg.w);
            hn[0] = sigf(go.x) * tanhx(cst[0]);
            hn[1] = sigf(go.y) * tanhx(cst[1]);
            hn[2] = sigf(go.z) * tanhx(cst[2]);
            hn[3] = sigf(go.w) * tanhx(cst[3]);
            float h0 = __bfloat162float(__float2bfloat16(hn[0]));
            float h1 = __bfloat162float(__float2bfloat16(hn[1]));
            float h2 = __bfloat162float(__float2bfloat16(hn[2]));
            float h3 = __bfloat162float(__float2bfloat16(hn[3]));
            uint2 HV, LV;
            HV.x = pk2(hn[0], hn[1]); HV.y = pk2(hn[2], hn[3]);
            LV.x = pk2(hn[0] - h0, hn[1] - h1); LV.y = pk2(hn[2] - h2, hn[3] - h3);
            __stcg(reinterpret_cast<uint2*>(&g_hh[s & 1][g][er][slice * 16 + u0]), HV);
            __stcg(reinterpret_cast<uint2*>(&g_hl[s & 1][g][er][slice * 16 + u0]), LV);
        }

        // ===== P7: sync + barrier arrive =====
        __syncthreads();
        if (tid == 0) {
            __threadfence();
            int prev = atomicAdd(&g_bar_count[g], 1);
            if (prev == NSLICE - 1) {
                atomicExch(&g_bar_count[g], 0);
                __threadfence();
                atomicExch(&g_bar_sense[g], (s & 1) ^ 1);
            }
        }
    }

    // ---- final barrier wait (round 511 sets sense 0) ----
    if (tid == 0) {
        volatile int* sp = &g_bar_sense[g];
        while (*sp != 0) __nanosleep(32);
        __threadfence();
    }
    __syncthreads();

    // ---- final projection (slice 0): out = h_n @ W_out^T + b_out ----
    if (slice == 0) {
        const int buf = (SEQ - 1) & 1;
        const float bo = b_out[0];
        for (int r8 = 0; r8 < 8; ++r8) {
            int r = wid * 8 + r8;
            int c0 = lane * 8;
            uint4 hv = __ldcg(reinterpret_cast<const uint4*>(&g_hh[buf][g][r][c0]));
            uint4 lv = __ldcg(reinterpret_cast<const uint4*>(&g_hl[buf][g][r][c0]));
            float acc = 0.0f;
            const uint32_t* hp = &hv.x;
            const uint32_t* lp = &lv.x;
            #pragma unroll
            for (int q = 0; q < 4; ++q) {
                float2 h2 = __bfloat1622float2(*reinterpret_cast<const __nv_bfloat162*>(&hp[q]));
                float2 l2 = __bfloat1622float2(*reinterpret_cast<const __nv_bfloat162*>(&lp[q]));
                acc += (h2.x + l2.x) * W_out[c0 + 2 * q]
                     + (h2.y + l2.y) * W_out[c0 + 2 * q + 1];
            }
            #pragma unroll
            for (int off = 16; off > 0; off >>= 1)
                acc += __shfl_xor_sync(0xFFFFFFFFu, acc, off);
            if (lane == 0) out[g * MR + r] = acc + bo;
        }
    }
}

// ---------------------------------------------------------------------------
extern "C" void kernel_launch(void* const* d_in, const int* in_sizes, int n_in,
                              void* d_out, int out_size) {
    const float* x     = (const float*)d_in[0];
    const float* W_ih  = (const float*)d_in[1];
    const float* W_hh  = (const float*)d_in[2];
    const float* b_ih  = (const float*)d_in[3];
    const float* b_hh  = (const float*)d_in[4];
    const float* W_out = (const float*)d_in[5];
    const float* b_out = (const float*)d_in[6];
    float* out = (float*)d_out;

    prep_x<<<2048, 256>>>(x);
    cudaFuncSetAttribute(lstm_mma,
                         cudaFuncAttributeMaxDynamicSharedMemorySize, SMEM_BYTES);
    lstm_mma<<<NCTA, NTHR, SMEM_BYTES>>>(W_ih, W_hh, b_ih, b_hh,
                                         W_out, b_out, out);
}

// round 11
// speedup vs baseline: 1.7236x; 1.0917x over previous
#include <cuda_runtime.h>
#include <cuda_bf16.h>
#include <cstdint>

// ---------------------------------------------------------------------------
// Round 11: in-register epilogue via gate-interleaved B columns.
// Geometry: 16 batch-groups (M=32) x 8 slices (N=128) = 128 CTAs, 1/SM.
// B column n = 16nq+8nt+2q+e  <->  gate (2nt+e) of unit (4nq+q): each thread's
// MMA C-fragments are {i,f,g,o} x 4 rows of ONE unit -> LSTM cell update runs
// on registers, no smem gate staging. Barrier uses release/acquire atomics.
// Math: 3-pass bf16-split mma.sync (A_hi*B_hi + A_lo*B_hi + A_hi*B_lo).
// ---------------------------------------------------------------------------

#define SEQ     512
#define BATCH   512
#define INPUT   128
#define HIDDEN  256
#define NGROUP  16
#define NSLICE  8
#define NCTA    128
#define NTHR    256
#define MR      32
#define NC      128
#define KTOT    384

// smem layout (bytes)
#define BPITCH  784
#define XPITCH  272
#define HPITCH  528
#define BLO_O   0            // 128*784 = 100352
#define AX_O    100352       // x hi (8704)
#define AXL_O   109056       // x lo (8704)
#define AH_O    117760       // h hi (16896)
#define AHL_O   134656       // h lo (16896)
#define SMEM_BYTES 151552

__device__ __align__(16) __nv_bfloat16 g_xhi[SEQ * BATCH * INPUT];
__device__ __align__(16) __nv_bfloat16 g_xlo[SEQ * BATCH * INPUT];
__device__ __align__(16) __nv_bfloat16 g_hh[2][NGROUP][MR][HIDDEN];
__device__ __align__(16) __nv_bfloat16 g_hl[2][NGROUP][MR][HIDDEN];
__device__ int g_bar_count[NGROUP];
__device__ int g_bar_sense[NGROUP];

// ---------------------------------------------------------------------------
__device__ __forceinline__ uint32_t smem_u32(const void* p) {
    uint32_t a;
    asm("{ .reg .u64 t; cvta.to.shared.u64 t, %1; cvt.u32.u64 %0, t; }"
        : "=r"(a) : "l"(p));
    return a;
}
__device__ __forceinline__ void ldsm4(uint32_t* r, uint32_t addr) {
    asm volatile("ldmatrix.sync.aligned.m8n8.x4.shared.b16 {%0,%1,%2,%3}, [%4];"
        : "=r"(r[0]), "=r"(r[1]), "=r"(r[2]), "=r"(r[3]) : "r"(addr));
}
__device__ __forceinline__ void ldsm2(uint32_t* r, uint32_t addr) {
    asm volatile("ldmatrix.sync.aligned.m8n8.x2.shared.b16 {%0,%1}, [%2];"
        : "=r"(r[0]), "=r"(r[1]) : "r"(addr));
}
__device__ __forceinline__ void mma_bf16(float* d, const uint32_t* a,
                                         const uint32_t* b) {
    asm volatile("mma.sync.aligned.m16n8k16.row.col.f32.bf16.bf16.f32 "
        "{%0,%1,%2,%3}, {%4,%5,%6,%7}, {%8,%9}, {%0,%1,%2,%3};"
        : "+f"(d[0]), "+f"(d[1]), "+f"(d[2]), "+f"(d[3])
        : "r"(a[0]), "r"(a[1]), "r"(a[2]), "r"(a[3]), "r"(b[0]), "r"(b[1]));
}
__device__ __forceinline__ void cpasync16(uint32_t dst, const void* src) {
    asm volatile("cp.async.cg.shared.global [%0], [%1], 16;"
        :: "r"(dst), "l"(src));
}
#define CP_COMMIT() asm volatile("cp.async.commit_group;" ::: "memory")
#define CP_WAIT0()  asm volatile("cp.async.wait_group 0;" ::: "memory")
#define CP_WAIT1()  asm volatile("cp.async.wait_group 1;" ::: "memory")

__device__ __forceinline__ int atom_add_release(int* p) {
    int prev;
    asm volatile("atom.release.gpu.global.add.u32 %0, [%1], 1;"
                 : "=r"(prev) : "l"(p) : "memory");
    return prev;
}
__device__ __forceinline__ void atom_exch_release(int* p, int v) {
    int old;
    asm volatile("atom.release.gpu.global.exch.b32 %0, [%1], %2;"
                 : "=r"(old) : "l"(p), "r"(v) : "memory");
}
__device__ __forceinline__ int ld_acquire(const int* p) {
    int v;
    asm volatile("ld.acquire.gpu.global.u32 %0, [%1];"
                 : "=r"(v) : "l"(p) : "memory");
    return v;
}

__device__ __forceinline__ float sigf(float v)  { return 1.0f / (1.0f + __expf(-v)); }
__device__ __forceinline__ float tanhx(float v) { return 2.0f / (1.0f + __expf(-2.0f * v)) - 1.0f; }
__device__ __forceinline__ uint32_t pk2(float a, float b) {
    __nv_bfloat162 t = __floats2bfloat162_rn(a, b);
    return *reinterpret_cast<uint32_t*>(&t);
}

// ---------------------------------------------------------------------------
__global__ void prep_x(const float* __restrict__ x) {
    const int N4 = SEQ * BATCH * INPUT / 4;
    for (int i = blockIdx.x * blockDim.x + threadIdx.x; i < N4;
         i += gridDim.x * blockDim.x) {
        float4 v = *reinterpret_cast<const float4*>(x + 4 * i);
        float hx = __bfloat162float(__float2bfloat16(v.x));
        float hy = __bfloat162float(__float2bfloat16(v.y));
        float hz = __bfloat162float(__float2bfloat16(v.z));
        float hw = __bfloat162float(__float2bfloat16(v.w));
        uint2 hi, lo;
        hi.x = pk2(v.x, v.y); hi.y = pk2(v.z, v.w);
        lo.x = pk2(v.x - hx, v.y - hy); lo.y = pk2(v.z - hz, v.w - hw);
        reinterpret_cast<uint2*>(g_xhi)[i] = hi;
        reinterpret_cast<uint2*>(g_xlo)[i] = lo;
    }
}

// ---------------------------------------------------------------------------
// CTA-local gate column n -> global gate row index in W (gcol).
// n = 16*nq + 8*nt + 2*q + e  ->  gate = 2*nt + e, unit = 4*nq + q.
__device__ __forceinline__ int map_gcol(int n, int slice) {
    int nq = n >> 4, nt = (n >> 3) & 1, q = (n >> 1) & 3, e = n & 1;
    int gate = 2 * nt + e;
    int unit = 4 * nq + q;
    return gate * HIDDEN + slice * 32 + unit;
}

__global__ void __launch_bounds__(NTHR, 1)
lstm_mma(const float* __restrict__ W_ih, const float* __restrict__ W_hh,
         const float* __restrict__ b_ih, const float* __restrict__ b_hh,
         const float* __restrict__ W_out, const float* __restrict__ b_out,
         float* __restrict__ out) {
    extern __shared__ char smem[];
    const uint32_t sA = smem_u32(smem);

    const int tid  = threadIdx.x;
    const int wid  = tid >> 5;
    const int lane = tid & 31;
    const int g     = blockIdx.x >> 3;    // batch group: rows g*32..
    const int slice = blockIdx.x & 7;     // hidden units slice*32..
    const int nq = wid;                   // warp n-strip: cols 16*nq..
    const int l15 = lane & 15;

    // ---- build B_lo (gate-interleaved columns) ----
    for (int i = tid; i < NC * KTOT; i += NTHR) {
        int n = i / KTOT, k = i - n * KTOT;
        int gcol = map_gcol(n, slice);
        float wv = (k < INPUT) ? W_ih[(size_t)gcol * INPUT + k]
                               : W_hh[(size_t)gcol * HIDDEN + (k - INPUT)];
        __nv_bfloat16 bhv = __float2bfloat16(wv);
        __nv_bfloat16 blv = __float2bfloat16(wv - __bfloat162float(bhv));
        *reinterpret_cast<__nv_bfloat16*>(smem + BLO_O + n * BPITCH + 2 * k) = blv;
    }

    // ---- B_hi -> registers, 2 staging phases of 64 cols (alias at AX_O) ----
    uint32_t bh[24][2][2];
    #pragma unroll
    for (int p = 0; p < 2; ++p) {
        __syncthreads();
        for (int i = tid; i < 64 * KTOT; i += NTHR) {
            int n = i / KTOT, k = i - n * KTOT;
            int gcol = map_gcol(p * 64 + n, slice);
            float wv = (k < INPUT) ? W_ih[(size_t)gcol * INPUT + k]
                                   : W_hh[(size_t)gcol * HIDDEN + (k - INPUT)];
            *reinterpret_cast<__nv_bfloat16*>(smem + AX_O + n * BPITCH + 2 * k) =
                __float2bfloat16(wv);
        }
        __syncthreads();
        if ((nq >> 2) == p) {
            int nloc = 16 * (nq & 3);
            uint32_t base = sA + AX_O + (uint32_t)(nloc + (l15 & 7)) * BPITCH
                          + (uint32_t)((l15 >> 3) & 1) * 16;
            #pragma unroll
            for (int kt = 0; kt < 24; ++kt) {
                ldsm2(&bh[kt][0][0], base + kt * 32);
                ldsm2(&bh[kt][1][0], base + 8 * BPITCH + kt * 32);
            }
        }
    }
    __syncthreads();

    // ---- zero h planes (h=0 for step 0) ----
    for (int i = tid; i < (SMEM_BYTES - AH_O) / 4; i += NTHR)
        reinterpret_cast<uint32_t*>(smem + AH_O)[i] = 0;

    // ---- stage x[0] (commit as group X) ----
    {
        const __nv_bfloat16* xh_ = g_xhi + (size_t)(g * MR) * INPUT;
        const __nv_bfloat16* xl_ = g_xlo + (size_t)(g * MR) * INPUT;
        for (int i = tid; i < MR * 16; i += NTHR) {
            int r = i >> 4, ch = i & 15;
            uint32_t dst = sA + AX_O + r * XPITCH + ch * 16;
            cpasync16(dst, xh_ + r * INPUT + ch * 8);
            cpasync16(dst + (AXL_O - AX_O), xl_ + r * INPUT + ch * 8);
        }
        CP_COMMIT();   // group X (for s=0)
    }

    // ---- per-lane ldmatrix bases ----
    const uint32_t baseX  = sA + AX_O + (uint32_t)l15 * XPITCH
                          + (uint32_t)(lane >> 4) * 16;
    const uint32_t baseH  = sA + AH_O + (uint32_t)l15 * HPITCH
                          + (uint32_t)(lane >> 4) * 16;
    const uint32_t baseBL = sA + BLO_O + (uint32_t)(16 * nq + (l15 & 7)) * BPITCH
                          + (uint32_t)((l15 >> 3) & 1) * 16;

    // ---- bias C init (new mapping): cb[nt][e] ----
    const int q = lane & 3;
    const int unit_l = 4 * nq + q;             // local unit 0..31
    const int gunit = slice * 32 + unit_l;     // global unit
    float cb[2][2];
    #pragma unroll
    for (int nt = 0; nt < 2; ++nt)
        #pragma unroll
        for (int e = 0; e < 2; ++e) {
            int gcol = (2 * nt + e) * HIDDEN + gunit;
            cb[nt][e] = b_ih[gcol] + b_hh[gcol];
        }

    float cst[4] = {0.f, 0.f, 0.f, 0.f};       // c-state: (mt,h) pairs

    for (int s = 0; s < SEQ; ++s) {
        // ===== A: acquire-poll group barrier for h(s-1) =====
        if (s > 0 && tid == 0) {
            int tgt = s & 1;
            while (ld_acquire(&g_bar_sense[g]) != tgt) __nanosleep(32);
        }
        // ===== B: issue cp.async h(s-1) [group H] =====
        // (safe: h buffers consumed last step; bar below orders vs peers)
        __syncthreads();
        if (s > 0) {
            const __nv_bfloat16* hh = &g_hh[(s - 1) & 1][g][0][0];
            const __nv_bfloat16* hl = &g_hl[(s - 1) & 1][g][0][0];
            for (int i = tid; i < MR * 32; i += NTHR) {
                int r = i >> 5, ch = i & 31;
                uint32_t dst = sA + AH_O + r * HPITCH + ch * 16;
                cpasync16(dst, hh + r * HIDDEN + ch * 8);
                cpasync16(dst + (AHL_O - AH_O), hl + r * HIDDEN + ch * 8);
            }
        }
        CP_COMMIT();                       // group H
        CP_WAIT1();                        // drain X (x(s) ready); H in flight
        __syncthreads();

        // ===== C: x-part MMAs (kt 0..7) — cover the h copy =====
        float d[2][2][4];
        #pragma unroll
        for (int mt = 0; mt < 2; ++mt)
            #pragma unroll
            for (int nt = 0; nt < 2; ++nt) {
                d[mt][nt][0] = cb[nt][0]; d[mt][nt][1] = cb[nt][1];
                d[mt][nt][2] = cb[nt][0]; d[mt][nt][3] = cb[nt][1];
            }
        #pragma unroll
        for (int kt = 0; kt < 8; ++kt) {
            uint32_t ah0[4], ah1[4], al0[4], al1[4], bl0[2], bl1[2];
            ldsm4(ah0, baseX + kt * 32);
            ldsm4(ah1, baseX + 16 * XPITCH + kt * 32);
            ldsm4(al0, baseX + (AXL_O - AX_O) + kt * 32);
            ldsm4(al1, baseX + (AXL_O - AX_O) + 16 * XPITCH + kt * 32);
            ldsm2(bl0, baseBL + kt * 32);
            ldsm2(bl1, baseBL + 8 * BPITCH + kt * 32);
            mma_bf16(d[0][0], ah0, bh[kt][0]); mma_bf16(d[0][1], ah0, bh[kt][1]);
            mma_bf16(d[1][0], ah1, bh[kt][0]); mma_bf16(d[1][1], ah1, bh[kt][1]);
            mma_bf16(d[0][0], al0, bh[kt][0]); mma_bf16(d[0][1], al0, bh[kt][1]);
            mma_bf16(d[1][0], al1, bh[kt][0]); mma_bf16(d[1][1], al1, bh[kt][1]);
            mma_bf16(d[0][0], ah0, bl0); mma_bf16(d[0][1], ah0, bl1);
            mma_bf16(d[1][0], ah1, bl0); mma_bf16(d[1][1], ah1, bl1);
        }

        // ===== D: wait H; sync; prefetch x(s+1) into AX =====
        CP_WAIT0();
        __syncthreads();   // H visible to all; AX consumed by all
        if (s + 1 < SEQ) {
            const __nv_bfloat16* xh_ = g_xhi + ((size_t)(s + 1) * BATCH + g * MR) * INPUT;
            const __nv_bfloat16* xl_ = g_xlo + ((size_t)(s + 1) * BATCH + g * MR) * INPUT;
            for (int i = tid; i < MR * 16; i += NTHR) {
                int r = i >> 4, ch = i & 15;
                uint32_t dst = sA + AX_O + r * XPITCH + ch * 16;
                cpasync16(dst, xh_ + r * INPUT + ch * 8);
                cpasync16(dst + (AXL_O - AX_O), xl_ + r * INPUT + ch * 8);
            }
        }
        CP_COMMIT();                       // group X (drained next step)

        // ===== E: h-part MMAs (kt 8..23) =====
        #pragma unroll
        for (int kt = 8; kt < 24; ++kt) {
            uint32_t ah0[4], ah1[4], al0[4], al1[4], bl0[2], bl1[2];
            uint32_t ko = (kt - 8) * 32;
            ldsm4(ah0, baseH + ko);
            ldsm4(ah1, baseH + 16 * HPITCH + ko);
            ldsm4(al0, baseH + (AHL_O - AH_O) + ko);
            ldsm4(al1, baseH + (AHL_O - AH_O) + 16 * HPITCH + ko);
            ldsm2(bl0, baseBL + kt * 32);
            ldsm2(bl1, baseBL + 8 * BPITCH + kt * 32);
            mma_bf16(d[0][0], ah0, bh[kt][0]); mma_bf16(d[0][1], ah0, bh[kt][1]);
            mma_bf16(d[1][0], ah1, bh[kt][0]); mma_bf16(d[1][1], ah1, bh[kt][1]);
            mma_bf16(d[0][0], al0, bh[kt][0]); mma_bf16(d[0][1], al0, bh[kt][1]);
            mma_bf16(d[1][0], al1, bh[kt][0]); mma_bf16(d[1][1], al1, bh[kt][1]);
            mma_bf16(d[0][0], ah0, bl0); mma_bf16(d[0][1], ah0, bl1);
            mma_bf16(d[1][0], ah1, bl0); mma_bf16(d[1][1], ah1, bl1);
        }

        // ===== F: IN-REGISTER epilogue — fragments ARE the gates =====
        // d[mt][nt][2h+e] = gate(2nt+e) of unit `gunit` at row 16mt+8h+(lane>>2)
        {
            __nv_bfloat16* hh = &g_hh[s & 1][g][0][0];
            __nv_bfloat16* hl = &g_hl[s & 1][g][0][0];
            #pragma unroll
            for (int mt = 0; mt < 2; ++mt)
                #pragma unroll
                for (int h2 = 0; h2 < 2; ++h2) {
                    float iv = d[mt][0][2 * h2 + 0];
                    float fv = d[mt][0][2 * h2 + 1];
                    float gv = d[mt][1][2 * h2 + 0];
                    float ov = d[mt][1][2 * h2 + 1];
                    int ci = 2 * mt + h2;
                    cst[ci] = sigf(fv) * cst[ci] + sigf(iv) * tanhx(gv);
                    float hn = sigf(ov) * tanhx(cst[ci]);
                    __nv_bfloat16 hb = __float2bfloat16(hn);
                    __nv_bfloat16 lb = __float2bfloat16(hn - __bfloat162float(hb));
                    int r = 16 * mt + 8 * h2 + (lane >> 2);
                    hh[r * HIDDEN + gunit] = hb;
                    hl[r * HIDDEN + gunit] = lb;
                }
        }

        // ===== G: bar + release-arrive =====
        __syncthreads();
        if (tid == 0) {
            int prev = atom_add_release(&g_bar_count[g]);
            if (prev == NSLICE - 1) {
                g_bar_count[g] = 0;                      // plain; ordered by release below
                atom_exch_release(&g_bar_sense[g], (s & 1) ^ 1);
            }
        }
    }

    // ---- final barrier wait (round 511 sets sense 0) ----
    if (tid == 0) {
        while (ld_acquire(&g_bar_sense[g]) != 0) __nanosleep(32);
    }
    __syncthreads();

    // ---- final projection (slice 0): out = h_n @ W_out^T + b_out ----
    if (slice == 0) {
        const int buf = (SEQ - 1) & 1;
        const float bo = b_out[0];
        for (int r4 = 0; r4 < 4; ++r4) {
            int r = wid * 4 + r4;               // 8 warps x 4 = 32 rows
            int c0 = lane * 8;
            uint4 hv = __ldcg(reinterpret_cast<const uint4*>(&g_hh[buf][g][r][c0]));
            uint4 lv = __ldcg(reinterpret_cast<const uint4*>(&g_hl[buf][g][r][c0]));
            float acc = 0.0f;
            const uint32_t* hp = &hv.x;
            const uint32_t* lp = &lv.x;
            #pragma unroll
            for (int qq = 0; qq < 4; ++qq) {
                float2 h2 = __bfloat1622float2(*reinterpret_cast<const __nv_bfloat162*>(&hp[qq]));
                float2 l2 = __bfloat1622float2(*reinterpret_cast<const __nv_bfloat162*>(&lp[qq]));
                acc += (h2.x + l2.x) * W_out[c0 + 2 * qq]
                     + (h2.y + l2.y) * W_out[c0 + 2 * qq + 1];
            }
            #pragma unroll
            for (int off = 16; off > 0; off >>= 1)
                acc += __shfl_xor_sync(0xFFFFFFFFu, acc, off);
            if (lane == 0) out[g * MR + r] = acc + bo;
        }
    }
}

// ---------------------------------------------------------------------------
extern "C" void kernel_launch(void* const* d_in, const int* in_sizes, int n_in,
                              void* d_out, int out_size) {
    const float* x     = (const float*)d_in[0];
    const float* W_ih  = (const float*)d_in[1];
    const float* W_hh  = (const float*)d_in[2];
    const float* b_ih  = (const float*)d_in[3];
    const float* b_hh  = (const float*)d_in[4];
    const float* W_out = (const float*)d_in[5];
    const float* b_out = (const float*)d_in[6];
    float* out = (float*)d_out;

    prep_x<<<2048, 256>>>(x);
    cudaFuncSetAttribute(lstm_mma,
                         cudaFuncAttributeMaxDynamicSharedMemorySize, SMEM_BYTES);
    lstm_mma<<<NCTA, NTHR, SMEM_BYTES>>>(W_ih, W_hh, b_ih, b_hh,
                                         W_out, b_out, out);
}

// round 12
// speedup vs baseline: 1.7270x; 1.0020x over previous
#include <cuda_runtime.h>
#include <cuda_bf16.h>
#include <cstdint>

// ---------------------------------------------------------------------------
// Round 12: warp-specialized exchange. 288 threads = 8 compute warps + 1
// exchange warp. Exchange warp: sense poll, cp.async h(s-1), x(s+1) prefetch,
// global group arrive. Compute warps: pure MMA/epilogue loop, local named-
// barrier handshakes only. h and x double-buffered in smem.
// Math unchanged (round 11): 3-pass bf16-split mma.sync, gate-interleaved B,
// in-register epilogue, B_hi register-resident.
// Geometry: 16 batch-groups (M=32) x 8 slices (N=128) = 128 CTAs, 1/SM.
// ---------------------------------------------------------------------------

#define SEQ     512
#define BATCH   512
#define INPUT   128
#define HIDDEN  256
#define NGROUP  16
#define NSLICE  8
#define NCTA    128
#define NTHR    288
#define MR      32
#define NC      128
#define KTOT    384

// smem layout (bytes)
#define BPITCH  784
#define XPITCH  272
#define HPITCH  528
#define BLO_O   0            // 128*784 = 100352
#define XB0     100352       // x: 2 bufs x (hi 8704 + lo 8704)
#define XBSTRIDE 17408
#define XLOFF   8704
#define HB0     135168       // h: 2 bufs x (hi 16896 + lo 16896)
#define HBSTRIDE 33792
#define HLOFF   16896
#define SMEM_BYTES 202752

__device__ __align__(16) __nv_bfloat16 g_xhi[SEQ * BATCH * INPUT];
__device__ __align__(16) __nv_bfloat16 g_xlo[SEQ * BATCH * INPUT];
__device__ __align__(16) __nv_bfloat16 g_hh[2][NGROUP][MR][HIDDEN];
__device__ __align__(16) __nv_bfloat16 g_hl[2][NGROUP][MR][HIDDEN];
__device__ int g_bar_count[NGROUP];
__device__ int g_bar_sense[NGROUP];

// ---------------------------------------------------------------------------
__device__ __forceinline__ uint32_t smem_u32(const void* p) {
    uint32_t a;
    asm("{ .reg .u64 t; cvta.to.shared.u64 t, %1; cvt.u32.u64 %0, t; }"
        : "=r"(a) : "l"(p));
    return a;
}
__device__ __forceinline__ void ldsm4(uint32_t* r, uint32_t addr) {
    asm volatile("ldmatrix.sync.aligned.m8n8.x4.shared.b16 {%0,%1,%2,%3}, [%4];"
        : "=r"(r[0]), "=r"(r[1]), "=r"(r[2]), "=r"(r[3]) : "r"(addr));
}
__device__ __forceinline__ void ldsm2(uint32_t* r, uint32_t addr) {
    asm volatile("ldmatrix.sync.aligned.m8n8.x2.shared.b16 {%0,%1}, [%2];"
        : "=r"(r[0]), "=r"(r[1]) : "r"(addr));
}
__device__ __forceinline__ void mma_bf16(float* d, const uint32_t* a,
                                         const uint32_t* b) {
    asm volatile("mma.sync.aligned.m16n8k16.row.col.f32.bf16.bf16.f32 "
        "{%0,%1,%2,%3}, {%4,%5,%6,%7}, {%8,%9}, {%0,%1,%2,%3};"
        : "+f"(d[0]), "+f"(d[1]), "+f"(d[2]), "+f"(d[3])
        : "r"(a[0]), "r"(a[1]), "r"(a[2]), "r"(a[3]), "r"(b[0]), "r"(b[1]));
}
__device__ __forceinline__ void cpasync16(uint32_t dst, const void* src) {
    asm volatile("cp.async.cg.shared.global [%0], [%1], 16;"
        :: "r"(dst), "l"(src));
}
#define CP_COMMIT() asm volatile("cp.async.commit_group;" ::: "memory")
#define CP_WAIT0()  asm volatile("cp.async.wait_group 0;" ::: "memory")

#define BAR_SYNC(id)   asm volatile("bar.sync %0, %1;" :: "r"(id), "r"(NTHR) : "memory")
#define BAR_ARRIVE(id) asm volatile("bar.arrive %0, %1;" :: "r"(id), "r"(NTHR) : "memory")

__device__ __forceinline__ int atom_add_release(int* p) {
    int prev;
    asm volatile("atom.release.gpu.global.add.u32 %0, [%1], 1;"
                 : "=r"(prev) : "l"(p) : "memory");
    return prev;
}
__device__ __forceinline__ void atom_exch_release(int* p, int v) {
    int old;
    asm volatile("atom.release.gpu.global.exch.b32 %0, [%1], %2;"
                 : "=r"(old) : "l"(p), "r"(v) : "memory");
}
__device__ __forceinline__ int ld_acquire(const int* p) {
    int v;
    asm volatile("ld.acquire.gpu.global.u32 %0, [%1];"
                 : "=r"(v) : "l"(p) : "memory");
    return v;
}

__device__ __forceinline__ float sigf(float v)  { return 1.0f / (1.0f + __expf(-v)); }
__device__ __forceinline__ float tanhx(float v) { return 2.0f / (1.0f + __expf(-2.0f * v)) - 1.0f; }
__device__ __forceinline__ uint32_t pk2(float a, float b) {
    __nv_bfloat162 t = __floats2bfloat162_rn(a, b);
    return *reinterpret_cast<uint32_t*>(&t);
}

// ---------------------------------------------------------------------------
__global__ void prep_x(const float* __restrict__ x) {
    const int N4 = SEQ * BATCH * INPUT / 4;
    for (int i = blockIdx.x * blockDim.x + threadIdx.x; i < N4;
         i += gridDim.x * blockDim.x) {
        float4 v = *reinterpret_cast<const float4*>(x + 4 * i);
        float hx = __bfloat162float(__float2bfloat16(v.x));
        float hy = __bfloat162float(__float2bfloat16(v.y));
        float hz = __bfloat162float(__float2bfloat16(v.z));
        float hw = __bfloat162float(__float2bfloat16(v.w));
        uint2 hi, lo;
        hi.x = pk2(v.x, v.y); hi.y = pk2(v.z, v.w);
        lo.x = pk2(v.x - hx, v.y - hy); lo.y = pk2(v.z - hz, v.w - hw);
        reinterpret_cast<uint2*>(g_xhi)[i] = hi;
        reinterpret_cast<uint2*>(g_xlo)[i] = lo;
    }
}

// ---------------------------------------------------------------------------
// CTA-local gate column n -> global gate row (gate-interleaved mapping).
// n = 16*nq + 8*nt + 2*q + e  ->  gate = 2*nt + e, unit = 4*nq + q.
__device__ __forceinline__ int map_gcol(int n, int slice) {
    int nq = n >> 4, nt = (n >> 3) & 1, q = (n >> 1) & 3, e = n & 1;
    return (2 * nt + e) * HIDDEN + slice * 32 + (4 * nq + q);
}

__global__ void __launch_bounds__(NTHR, 1)
lstm_mma(const float* __restrict__ W_ih, const float* __restrict__ W_hh,
         const float* __restrict__ b_ih, const float* __restrict__ b_hh,
         const float* __restrict__ W_out, const float* __restrict__ b_out,
         float* __restrict__ out) {
    extern __shared__ char smem[];
    const uint32_t sA = smem_u32(smem);

    const int tid  = threadIdx.x;
    const int wid  = tid >> 5;
    const int lane = tid & 31;
    const int g     = blockIdx.x >> 3;    // batch group
    const int slice = blockIdx.x & 7;     // hidden slice
    const bool is_x = (wid == 8);         // exchange warp
    const int nq = wid;                   // compute warp n-strip
    const int l15 = lane & 15;

    // ---- build B_lo (gate-interleaved columns) ----
    for (int i = tid; i < NC * KTOT; i += NTHR) {
        int n = i / KTOT, k = i - n * KTOT;
        int gcol = map_gcol(n, slice);
        float wv = (k < INPUT) ? W_ih[(size_t)gcol * INPUT + k]
                               : W_hh[(size_t)gcol * HIDDEN + (k - INPUT)];
        __nv_bfloat16 bhv = __float2bfloat16(wv);
        __nv_bfloat16 blv = __float2bfloat16(wv - __bfloat162float(bhv));
        *reinterpret_cast<__nv_bfloat16*>(smem + BLO_O + n * BPITCH + 2 * k) = blv;
    }

    // ---- B_hi -> compute-warp registers, 2 phases (alias x/h region) ----
    uint32_t bh[24][2][2];
    #pragma unroll
    for (int p = 0; p < 2; ++p) {
        __syncthreads();
        for (int i = tid; i < 64 * KTOT; i += NTHR) {
            int n = i / KTOT, k = i - n * KTOT;
            int gcol = map_gcol(p * 64 + n, slice);
            float wv = (k < INPUT) ? W_ih[(size_t)gcol * INPUT + k]
                                   : W_hh[(size_t)gcol * HIDDEN + (k - INPUT)];
            *reinterpret_cast<__nv_bfloat16*>(smem + XB0 + n * BPITCH + 2 * k) =
                __float2bfloat16(wv);
        }
        __syncthreads();
        if (!is_x && (nq >> 2) == p) {
            int nloc = 16 * (nq & 3);
            uint32_t base = sA + XB0 + (uint32_t)(nloc + (l15 & 7)) * BPITCH
                          + (uint32_t)((l15 >> 3) & 1) * 16;
            #pragma unroll
            for (int kt = 0; kt < 24; ++kt) {
                ldsm2(&bh[kt][0][0], base + kt * 32);
                ldsm2(&bh[kt][1][0], base + 8 * BPITCH + kt * 32);
            }
        }
    }
    __syncthreads();

    // ---- zero h buffer 0 (h = 0 at step 0) ----
    for (int i = tid; i < HBSTRIDE / 4; i += NTHR)
        reinterpret_cast<uint32_t*>(smem + HB0)[i] = 0;

    // ---- stage x[0] into x-buffer 0 (all threads) ----
    {
        const __nv_bfloat16* xh_ = g_xhi + (size_t)(g * MR) * INPUT;
        const __nv_bfloat16* xl_ = g_xlo + (size_t)(g * MR) * INPUT;
        for (int i = tid; i < MR * 16; i += NTHR) {
            int r = i >> 4, ch = i & 15;
            uint32_t dst = sA + XB0 + r * XPITCH + ch * 16;
            cpasync16(dst, xh_ + r * INPUT + ch * 8);
            cpasync16(dst + XLOFF, xl_ + r * INPUT + ch * 8);
        }
        CP_COMMIT();
        CP_WAIT0();
    }
    __syncthreads();

    if (is_x) {
        // =================== EXCHANGE WARP ===================
        for (int s = 0; s < SEQ; ++s) {
            // wait for h(s-1) to be globally published
            if (s > 0) {
                if (lane == 0) {
                    int tgt = s & 1;
                    while (ld_acquire(&g_bar_sense[g]) != tgt) __nanosleep(32);
                }
                __syncwarp();
                // copy h(s-1) -> hbuf[s&1]
                const __nv_bfloat16* hh = &g_hh[(s - 1) & 1][g][0][0];
                const __nv_bfloat16* hl = &g_hl[(s - 1) & 1][g][0][0];
                uint32_t hb = sA + HB0 + (uint32_t)(s & 1) * HBSTRIDE;
                for (int i = lane; i < MR * 32; i += 32) {
                    int r = i >> 5, ch = i & 31;
                    uint32_t dst = hb + r * HPITCH + ch * 16;
                    cpasync16(dst, hh + r * HIDDEN + ch * 8);
                    cpasync16(dst + HLOFF, hl + r * HIDDEN + ch * 8);
                }
            }
            // prefetch x(s+1) -> xbuf[(s+1)&1]
            if (s + 1 < SEQ) {
                const __nv_bfloat16* xh_ = g_xhi + ((size_t)(s + 1) * BATCH + g * MR) * INPUT;
                const __nv_bfloat16* xl_ = g_xlo + ((size_t)(s + 1) * BATCH + g * MR) * INPUT;
                uint32_t xb = sA + XB0 + (uint32_t)((s + 1) & 1) * XBSTRIDE;
                for (int i = lane; i < MR * 16; i += 32) {
                    int r = i >> 4, ch = i & 15;
                    uint32_t dst = xb + r * XPITCH + ch * 16;
                    cpasync16(dst, xh_ + r * INPUT + ch * 8);
                    cpasync16(dst + XLOFF, xl_ + r * INPUT + ch * 8);
                }
            }
            CP_COMMIT();
            CP_WAIT0();
            BAR_ARRIVE(1);     // h(s-1) + x(s+1) staged
            BAR_SYNC(2);       // wait compute epilogue (h(s) stores done)
            if (lane == 0) {
                int prev = atom_add_release(&g_bar_count[g]);
                if (prev == NSLICE - 1) {
                    g_bar_count[g] = 0;
                    atom_exch_release(&g_bar_sense[g], (s & 1) ^ 1);
                }
            }
            __syncwarp();
        }
        // final: wait all groups' round 511 (sense -> 0)
        if (lane == 0)
            while (ld_acquire(&g_bar_sense[g]) != 0) __nanosleep(32);
        __syncwarp();
    } else {
        // =================== COMPUTE WARPS ===================
        const uint32_t baseX  = sA + XB0 + (uint32_t)l15 * XPITCH
                              + (uint32_t)(lane >> 4) * 16;
        const uint32_t baseH  = sA + HB0 + (uint32_t)l15 * HPITCH
                              + (uint32_t)(lane >> 4) * 16;
        const uint32_t baseBL = sA + BLO_O + (uint32_t)(16 * nq + (l15 & 7)) * BPITCH
                              + (uint32_t)((l15 >> 3) & 1) * 16;

        const int q = lane & 3;
        const int gunit = slice * 32 + 4 * nq + q;
        float cb[2][2];
        #pragma unroll
        for (int nt = 0; nt < 2; ++nt)
            #pragma unroll
            for (int e = 0; e < 2; ++e) {
                int gcol = (2 * nt + e) * HIDDEN + gunit;
                cb[nt][e] = b_ih[gcol] + b_hh[gcol];
            }

        float cst[4] = {0.f, 0.f, 0.f, 0.f};

        for (int s = 0; s < SEQ; ++s) {
            // ---- x-part MMAs (kt 0..7) from xbuf[s&1] ----
            float d[2][2][4];
            #pragma unroll
            for (int mt = 0; mt < 2; ++mt)
                #pragma unroll
                for (int nt = 0; nt < 2; ++nt) {
                    d[mt][nt][0] = cb[nt][0]; d[mt][nt][1] = cb[nt][1];
                    d[mt][nt][2] = cb[nt][0]; d[mt][nt][3] = cb[nt][1];
                }
            {
                uint32_t bx = baseX + (uint32_t)(s & 1) * XBSTRIDE;
                #pragma unroll
                for (int kt = 0; kt < 8; ++kt) {
                    uint32_t ah0[4], ah1[4], al0[4], al1[4], bl0[2], bl1[2];
                    ldsm4(ah0, bx + kt * 32);
                    ldsm4(ah1, bx + 16 * XPITCH + kt * 32);
                    ldsm4(al0, bx + XLOFF + kt * 32);
                    ldsm4(al1, bx + XLOFF + 16 * XPITCH + kt * 32);
                    ldsm2(bl0, baseBL + kt * 32);
                    ldsm2(bl1, baseBL + 8 * BPITCH + kt * 32);
                    mma_bf16(d[0][0], ah0, bh[kt][0]); mma_bf16(d[0][1], ah0, bh[kt][1]);
                    mma_bf16(d[1][0], ah1, bh[kt][0]); mma_bf16(d[1][1], ah1, bh[kt][1]);
                    mma_bf16(d[0][0], al0, bh[kt][0]); mma_bf16(d[0][1], al0, bh[kt][1]);
                    mma_bf16(d[1][0], al1, bh[kt][0]); mma_bf16(d[1][1], al1, bh[kt][1]);
                    mma_bf16(d[0][0], ah0, bl0); mma_bf16(d[0][1], ah0, bl1);
                    mma_bf16(d[1][0], ah1, bl0); mma_bf16(d[1][1], ah1, bl1);
                }
            }

            BAR_SYNC(1);   // h(s-1) in hbuf[s&1]; x(s+1) staged

            // ---- h-part MMAs (kt 8..23) from hbuf[s&1] ----
            {
                uint32_t bhm = baseH + (uint32_t)(s & 1) * HBSTRIDE;
                #pragma unroll
                for (int kt = 8; kt < 24; ++kt) {
                    uint32_t ah0[4], ah1[4], al0[4], al1[4], bl0[2], bl1[2];
                    uint32_t ko = (kt - 8) * 32;
                    ldsm4(ah0, bhm + ko);
                    ldsm4(ah1, bhm + 16 * HPITCH + ko);
                    ldsm4(al0, bhm + HLOFF + ko);
                    ldsm4(al1, bhm + HLOFF + 16 * HPITCH + ko);
                    ldsm2(bl0, baseBL + kt * 32);
                    ldsm2(bl1, baseBL + 8 * BPITCH + kt * 32);
                    mma_bf16(d[0][0], ah0, bh[kt][0]); mma_bf16(d[0][1], ah0, bh[kt][1]);
                    mma_bf16(d[1][0], ah1, bh[kt][0]); mma_bf16(d[1][1], ah1, bh[kt][1]);
                    mma_bf16(d[0][0], al0, bh[kt][0]); mma_bf16(d[0][1], al0, bh[kt][1]);
                    mma_bf16(d[1][0], al1, bh[kt][0]); mma_bf16(d[1][1], al1, bh[kt][1]);
                    mma_bf16(d[0][0], ah0, bl0); mma_bf16(d[0][1], ah0, bl1);
                    mma_bf16(d[1][0], ah1, bl0); mma_bf16(d[1][1], ah1, bl1);
                }
            }

            // ---- in-register epilogue + publish h(s) ----
            {
                __nv_bfloat16* hh = &g_hh[s & 1][g][0][0];
                __nv_bfloat16* hl = &g_hl[s & 1][g][0][0];
                #pragma unroll
                for (int mt = 0; mt < 2; ++mt)
                    #pragma unroll
                    for (int h2 = 0; h2 < 2; ++h2) {
                        float iv = d[mt][0][2 * h2 + 0];
                        float fv = d[mt][0][2 * h2 + 1];
                        float gv = d[mt][1][2 * h2 + 0];
                        float ov = d[mt][1][2 * h2 + 1];
                        int ci = 2 * mt + h2;
                        cst[ci] = sigf(fv) * cst[ci] + sigf(iv) * tanhx(gv);
                        float hn = sigf(ov) * tanhx(cst[ci]);
                        __nv_bfloat16 hb = __float2bfloat16(hn);
                        __nv_bfloat16 lb = __float2bfloat16(hn - __bfloat162float(hb));
                        int r = 16 * mt + 8 * h2 + (lane >> 2);
                        hh[r * HIDDEN + gunit] = hb;
                        hl[r * HIDDEN + gunit] = lb;
                    }
            }

            BAR_ARRIVE(2);   // epilogue done; exchange warp publishes
        }
    }

    __syncthreads();   // all 288: exchange warp verified global completion

    // ---- final projection (slice 0, compute warps) ----
    if (slice == 0 && !is_x) {
        const int buf = (SEQ - 1) & 1;
        const float bo = b_out[0];
        for (int r4 = 0; r4 < 4; ++r4) {
            int r = wid * 4 + r4;
            int c0 = lane * 8;
            uint4 hv = __ldcg(reinterpret_cast<const uint4*>(&g_hh[buf][g][r][c0]));
            uint4 lv = __ldcg(reinterpret_cast<const uint4*>(&g_hl[buf][g][r][c0]));
            float acc = 0.0f;
            const uint32_t* hp = &hv.x;
            const uint32_t* lp = &lv.x;
            #pragma unroll
            for (int qq = 0; qq < 4; ++qq) {
                float2 h2 = __bfloat1622float2(*reinterpret_cast<const __nv_bfloat162*>(&hp[qq]));
                float2 l2 = __bfloat1622float2(*reinterpret_cast<const __nv_bfloat162*>(&lp[qq]));
                acc += (h2.x + l2.x) * W_out[c0 + 2 * qq]
                     + (h2.y + l2.y) * W_out[c0 + 2 * qq + 1];
            }
            #pragma unroll
            for (int off = 16; off > 0; off >>= 1)
                acc += __shfl_xor_sync(0xFFFFFFFFu, acc, off);
            if (lane == 0) out[g * MR + r] = acc + bo;
        }
    }
}

// ---------------------------------------------------------------------------
extern "C" void kernel_launch(void* const* d_in, const int* in_sizes, int n_in,
                              void* d_out, int out_size) {
    const float* x     = (const float*)d_in[0];
    const float* W_ih  = (const float*)d_in[1];
    const float* W_hh  = (const float*)d_in[2];
    const float* b_ih  = (const float*)d_in[3];
    const float* b_hh  = (const float*)d_in[4];
    const float* W_out = (const float*)d_in[5];
    const float* b_out = (const float*)d_in[6];
    float* out = (float*)d_out;

    prep_x<<<2048, 256>>>(x);
    cudaFuncSetAttribute(lstm_mma,
                         cudaFuncAttributeMaxDynamicSharedMemorySize, SMEM_BYTES);
    lstm_mma<<<NCTA, NTHR, SMEM_BYTES>>>(W_ih, W_hh, b_ih, b_hh,
                                         W_out, b_out, out);
}

// round 14
// speedup vs baseline: 2.0939x; 1.2124x over previous
#include <cuda_runtime.h>
#include <cuda_bf16.h>
#include <cstdint>

// ---------------------------------------------------------------------------
// Round 14 = Round 13 with the staging-tile pitch fixed (72 -> 80 bytes,
// 16B-aligned rows; the misaligned-address crash was LDS.128 at row*72).
//  (1) h published via smem staging tile -> coalesced STG.128
//  (2) per-producer release/acquire flags
//  (3) h copy split into two cp.async groups; first-half h-MMAs start early
// Math unchanged: 3-pass bf16-split mma.sync, gate-interleaved B columns,
// in-register epilogue, B_hi register-resident.
// Geometry: 16 batch-groups (M=32) x 8 slices (N=128) = 128 CTAs, 1/SM,
// 288 threads = 8 compute warps + 1 exchange warp.
// ---------------------------------------------------------------------------

#define SEQ     512
#define BATCH   512
#define INPUT   128
#define HIDDEN  256
#define NGROUP  16
#define NSLICE  8
#define NCTA    128
#define NTHR    288
#define MR      32
#define NC      128
#define KTOT    384

// smem layout (bytes)
#define BPITCH  784
#define XPITCH  272
#define HPITCH  528
#define BLO_O   0            // 128*784 = 100352
#define XB0     100352       // x: 2 bufs x (hi 8704 + lo 8704)
#define XBSTRIDE 17408
#define XLOFF   8704
#define HB0     135168       // h: 2 bufs x (hi 16896 + lo 16896)
#define HBSTRIDE 33792
#define HLOFF   16896
#define HSTG    202752       // h staging: 2 planes x 32 rows x 80B = 5120
#define HSTG_PITCH 80
#define HSTG_LO 2560
#define SMEM_BYTES 207872

__device__ __align__(16) __nv_bfloat16 g_xhi[SEQ * BATCH * INPUT];
__device__ __align__(16) __nv_bfloat16 g_xlo[SEQ * BATCH * INPUT];
__device__ __align__(16) __nv_bfloat16 g_hh[2][NGROUP][MR][HIDDEN];
__device__ __align__(16) __nv_bfloat16 g_hl[2][NGROUP][MR][HIDDEN];
__device__ int g_flag[NGROUP][NSLICE][32];   // one padded flag per producer

// ---------------------------------------------------------------------------
__device__ __forceinline__ uint32_t smem_u32(const void* p) {
    uint32_t a;
    asm("{ .reg .u64 t; cvta.to.shared.u64 t, %1; cvt.u32.u64 %0, t; }"
        : "=r"(a) : "l"(p));
    return a;
}
__device__ __forceinline__ void ldsm4(uint32_t* r, uint32_t addr) {
    asm volatile("ldmatrix.sync.aligned.m8n8.x4.shared.b16 {%0,%1,%2,%3}, [%4];"
        : "=r"(r[0]), "=r"(r[1]), "=r"(r[2]), "=r"(r[3]) : "r"(addr));
}
__device__ __forceinline__ void ldsm2(uint32_t* r, uint32_t addr) {
    asm volatile("ldmatrix.sync.aligned.m8n8.x2.shared.b16 {%0,%1}, [%2];"
        : "=r"(r[0]), "=r"(r[1]) : "r"(addr));
}
__device__ __forceinline__ void mma_bf16(float* d, const uint32_t* a,
                                         const uint32_t* b) {
    asm volatile("mma.sync.aligned.m16n8k16.row.col.f32.bf16.bf16.f32 "
        "{%0,%1,%2,%3}, {%4,%5,%6,%7}, {%8,%9}, {%0,%1,%2,%3};"
        : "+f"(d[0]), "+f"(d[1]), "+f"(d[2]), "+f"(d[3])
        : "r"(a[0]), "r"(a[1]), "r"(a[2]), "r"(a[3]), "r"(b[0]), "r"(b[1]));
}
__device__ __forceinline__ void cpasync16(uint32_t dst, const void* src) {
    asm volatile("cp.async.cg.shared.global [%0], [%1], 16;"
        :: "r"(dst), "l"(src));
}
#define CP_COMMIT() asm volatile("cp.async.commit_group;" ::: "memory")
#define CP_WAIT0()  asm volatile("cp.async.wait_group 0;" ::: "memory")
#define CP_WAIT2()  asm volatile("cp.async.wait_group 2;" ::: "memory")

#define BAR_SYNC(id, n)   asm volatile("bar.sync %0, %1;" :: "r"(id), "r"(n) : "memory")
#define BAR_ARRIVE(id, n) asm volatile("bar.arrive %0, %1;" :: "r"(id), "r"(n) : "memory")

__device__ __forceinline__ void st_release(int* p, int v) {
    asm volatile("st.release.gpu.global.b32 [%0], %1;"
                 :: "l"(p), "r"(v) : "memory");
}
__device__ __forceinline__ int ld_acquire(const int* p) {
    int v;
    asm volatile("ld.acquire.gpu.global.u32 %0, [%1];"
                 : "=r"(v) : "l"(p) : "memory");
    return v;
}

__device__ __forceinline__ float sigf(float v)  { return 1.0f / (1.0f + __expf(-v)); }
__device__ __forceinline__ float tanhx(float v) { return 2.0f / (1.0f + __expf(-2.0f * v)) - 1.0f; }
__device__ __forceinline__ uint32_t pk2(float a, float b) {
    __nv_bfloat162 t = __floats2bfloat162_rn(a, b);
    return *reinterpret_cast<uint32_t*>(&t);
}

// ---------------------------------------------------------------------------
__global__ void prep_x(const float* __restrict__ x) {
    const int N4 = SEQ * BATCH * INPUT / 4;
    for (int i = blockIdx.x * blockDim.x + threadIdx.x; i < N4;
         i += gridDim.x * blockDim.x) {
        float4 v = *reinterpret_cast<const float4*>(x + 4 * i);
        float hx = __bfloat162float(__float2bfloat16(v.x));
        float hy = __bfloat162float(__float2bfloat16(v.y));
        float hz = __bfloat162float(__float2bfloat16(v.z));
        float hw = __bfloat162float(__float2bfloat16(v.w));
        uint2 hi, lo;
        hi.x = pk2(v.x, v.y); hi.y = pk2(v.z, v.w);
        lo.x = pk2(v.x - hx, v.y - hy); lo.y = pk2(v.z - hz, v.w - hw);
        reinterpret_cast<uint2*>(g_xhi)[i] = hi;
        reinterpret_cast<uint2*>(g_xlo)[i] = lo;
    }
}

// ---------------------------------------------------------------------------
// CTA-local gate column n -> global gate row (gate-interleaved mapping).
// n = 16*nq + 8*nt + 2*q + e  ->  gate = 2*nt + e, unit = 4*nq + q.
__device__ __forceinline__ int map_gcol(int n, int slice) {
    int nq = n >> 4, nt = (n >> 3) & 1, q = (n >> 1) & 3, e = n & 1;
    return (2 * nt + e) * HIDDEN + slice * 32 + (4 * nq + q);
}

__global__ void __launch_bounds__(NTHR, 1)
lstm_mma(const float* __restrict__ W_ih, const float* __restrict__ W_hh,
         const float* __restrict__ b_ih, const float* __restrict__ b_hh,
         const float* __restrict__ W_out, const float* __restrict__ b_out,
         float* __restrict__ out) {
    extern __shared__ char smem[];
    const uint32_t sA = smem_u32(smem);

    const int tid  = threadIdx.x;
    const int wid  = tid >> 5;
    const int lane = tid & 31;
    const int g     = blockIdx.x >> 3;    // batch group
    const int slice = blockIdx.x & 7;     // hidden slice
    const bool is_x = (wid == 8);         // exchange warp
    const int nq = wid;                   // compute warp n-strip
    const int l15 = lane & 15;

    // ---- build B_lo (gate-interleaved columns) ----
    for (int i = tid; i < NC * KTOT; i += NTHR) {
        int n = i / KTOT, k = i - n * KTOT;
        int gcol = map_gcol(n, slice);
        float wv = (k < INPUT) ? W_ih[(size_t)gcol * INPUT + k]
                               : W_hh[(size_t)gcol * HIDDEN + (k - INPUT)];
        __nv_bfloat16 bhv = __float2bfloat16(wv);
        __nv_bfloat16 blv = __float2bfloat16(wv - __bfloat162float(bhv));
        *reinterpret_cast<__nv_bfloat16*>(smem + BLO_O + n * BPITCH + 2 * k) = blv;
    }

    // ---- B_hi -> compute-warp registers, 2 phases (alias x/h region) ----
    uint32_t bh[24][2][2];
    #pragma unroll
    for (int p = 0; p < 2; ++p) {
        __syncthreads();
        for (int i = tid; i < 64 * KTOT; i += NTHR) {
            int n = i / KTOT, k = i - n * KTOT;
            int gcol = map_gcol(p * 64 + n, slice);
            float wv = (k < INPUT) ? W_ih[(size_t)gcol * INPUT + k]
                                   : W_hh[(size_t)gcol * HIDDEN + (k - INPUT)];
            *reinterpret_cast<__nv_bfloat16*>(smem + XB0 + n * BPITCH + 2 * k) =
                __float2bfloat16(wv);
        }
        __syncthreads();
        if (!is_x && (nq >> 2) == p) {
            int nloc = 16 * (nq & 3);
            uint32_t base = sA + XB0 + (uint32_t)(nloc + (l15 & 7)) * BPITCH
                          + (uint32_t)((l15 >> 3) & 1) * 16;
            #pragma unroll
            for (int kt = 0; kt < 24; ++kt) {
                ldsm2(&bh[kt][0][0], base + kt * 32);
                ldsm2(&bh[kt][1][0], base + 8 * BPITCH + kt * 32);
            }
        }
    }
    __syncthreads();

    // ---- zero h buffer 0 (h = 0 at step 0) ----
    for (int i = tid; i < HBSTRIDE / 4; i += NTHR)
        reinterpret_cast<uint32_t*>(smem + HB0)[i] = 0;

    // ---- stage x[0] into x-buffer 0 (all threads) ----
    {
        const __nv_bfloat16* xh_ = g_xhi + (size_t)(g * MR) * INPUT;
        const __nv_bfloat16* xl_ = g_xlo + (size_t)(g * MR) * INPUT;
        for (int i = tid; i < MR * 16; i += NTHR) {
            int r = i >> 4, ch = i & 15;
            uint32_t dst = sA + XB0 + r * XPITCH + ch * 16;
            cpasync16(dst, xh_ + r * INPUT + ch * 8);
            cpasync16(dst + XLOFF, xl_ + r * INPUT + ch * 8);
        }
        CP_COMMIT();
        CP_WAIT0();
    }
    __syncthreads();

    if (is_x) {
        // =================== EXCHANGE WARP ===================
        for (int s = 0; s < SEQ; ++s) {
            const int tag = s & 1;       // tag published at step s-1
            const __nv_bfloat16* hh = &g_hh[(s - 1) & 1][g][0][0];
            const __nv_bfloat16* hl = &g_hl[(s - 1) & 1][g][0][0];
            uint32_t hb = sA + HB0 + (uint32_t)(s & 1) * HBSTRIDE;

            // phase A: producers 0..3 (h units 0..127)
            if (s > 0) {
                if (lane < 4)
                    while (ld_acquire(&g_flag[g][lane][0]) != tag) __nanosleep(16);
                __syncwarp();
                for (int i = lane; i < MR * 16; i += 32) {
                    int r = i >> 4, ch = i & 15;
                    uint32_t dst = hb + r * HPITCH + ch * 16;
                    cpasync16(dst, hh + r * HIDDEN + ch * 8);
                    cpasync16(dst + HLOFF, hl + r * HIDDEN + ch * 8);
                }
            }
            CP_COMMIT();     // group h1

            // phase B: producers 4..7 (h units 128..255)
            if (s > 0) {
                if (lane < 4)
                    while (ld_acquire(&g_flag[g][4 + lane][0]) != tag) __nanosleep(16);
                __syncwarp();
                for (int i = lane; i < MR * 16; i += 32) {
                    int r = i >> 4, ch = 16 + (i & 15);
                    uint32_t dst = hb + r * HPITCH + ch * 16;
                    cpasync16(dst, hh + r * HIDDEN + ch * 8);
                    cpasync16(dst + HLOFF, hl + r * HIDDEN + ch * 8);
                }
            }
            CP_COMMIT();     // group h2

            // x(s+1) prefetch
            if (s + 1 < SEQ) {
                const __nv_bfloat16* xh_ = g_xhi + ((size_t)(s + 1) * BATCH + g * MR) * INPUT;
                const __nv_bfloat16* xl_ = g_xlo + ((size_t)(s + 1) * BATCH + g * MR) * INPUT;
                uint32_t xb = sA + XB0 + (uint32_t)((s + 1) & 1) * XBSTRIDE;
                for (int i = lane; i < MR * 16; i += 32) {
                    int r = i >> 4, ch = i & 15;
                    uint32_t dst = xb + r * XPITCH + ch * 16;
                    cpasync16(dst, xh_ + r * INPUT + ch * 8);
                    cpasync16(dst + XLOFF, xl_ + r * INPUT + ch * 8);
                }
            }
            CP_COMMIT();     // group x

            CP_WAIT2();                  // h1 landed
            BAR_ARRIVE(3, NTHR);         // compute may run kt 8..15
            CP_WAIT0();                  // h2 + x landed
            BAR_ARRIVE(1, NTHR);         // compute may run kt 16..23 (+next x)
            BAR_SYNC(2, NTHR);           // compute epilogue + copy-out done
            if (lane == 0) {
                __threadfence();
                st_release(&g_flag[g][slice][0], tag ^ 1);
            }
            __syncwarp();
        }
        // final: all producers' step-511 publish (tag 0; prior value was 1)
        if (lane < 8)
            while (ld_acquire(&g_flag[g][lane][0]) != 0) __nanosleep(16);
        __syncwarp();
    } else {
        // =================== COMPUTE WARPS ===================
        const uint32_t baseX  = sA + XB0 + (uint32_t)l15 * XPITCH
                              + (uint32_t)(lane >> 4) * 16;
        const uint32_t baseH  = sA + HB0 + (uint32_t)l15 * HPITCH
                              + (uint32_t)(lane >> 4) * 16;
        const uint32_t baseBL = sA + BLO_O + (uint32_t)(16 * nq + (l15 & 7)) * BPITCH
                              + (uint32_t)((l15 >> 3) & 1) * 16;

        const int q = lane & 3;
        const int unit_l = 4 * nq + q;          // local unit 0..31
        const int gunit = slice * 32 + unit_l;  // global unit
        float cb[2][2];
        #pragma unroll
        for (int nt = 0; nt < 2; ++nt)
            #pragma unroll
            for (int e = 0; e < 2; ++e) {
                int gcol = (2 * nt + e) * HIDDEN + gunit;
                cb[nt][e] = b_ih[gcol] + b_hh[gcol];
            }

        float cst[4] = {0.f, 0.f, 0.f, 0.f};

        for (int s = 0; s < SEQ; ++s) {
            // ---- x-part MMAs (kt 0..7) from xbuf[s&1] ----
            float d[2][2][4];
            #pragma unroll
            for (int mt = 0; mt < 2; ++mt)
                #pragma unroll
                for (int nt = 0; nt < 2; ++nt) {
                    d[mt][nt][0] = cb[nt][0]; d[mt][nt][1] = cb[nt][1];
                    d[mt][nt][2] = cb[nt][0]; d[mt][nt][3] = cb[nt][1];
                }
            {
                uint32_t bx = baseX + (uint32_t)(s & 1) * XBSTRIDE;
                #pragma unroll
                for (int kt = 0; kt < 8; ++kt) {
                    uint32_t ah0[4], ah1[4], al0[4], al1[4], bl0[2], bl1[2];
                    ldsm4(ah0, bx + kt * 32);
                    ldsm4(ah1, bx + 16 * XPITCH + kt * 32);
                    ldsm4(al0, bx + XLOFF + kt * 32);
                    ldsm4(al1, bx + XLOFF + 16 * XPITCH + kt * 32);
                    ldsm2(bl0, baseBL + kt * 32);
                    ldsm2(bl1, baseBL + 8 * BPITCH + kt * 32);
                    mma_bf16(d[0][0], ah0, bh[kt][0]); mma_bf16(d[0][1], ah0, bh[kt][1]);
                    mma_bf16(d[1][0], ah1, bh[kt][0]); mma_bf16(d[1][1], ah1, bh[kt][1]);
                    mma_bf16(d[0][0], al0, bh[kt][0]); mma_bf16(d[0][1], al0, bh[kt][1]);
                    mma_bf16(d[1][0], al1, bh[kt][0]); mma_bf16(d[1][1], al1, bh[kt][1]);
                    mma_bf16(d[0][0], ah0, bl0); mma_bf16(d[0][1], ah0, bl1);
                    mma_bf16(d[1][0], ah1, bl0); mma_bf16(d[1][1], ah1, bl1);
                }
            }

            uint32_t bhm = baseH + (uint32_t)(s & 1) * HBSTRIDE;

            BAR_SYNC(3, NTHR);   // first half of h(s-1) staged

            // ---- h-part MMAs, first half (kt 8..15) ----
            #pragma unroll
            for (int kt = 8; kt < 16; ++kt) {
                uint32_t ah0[4], ah1[4], al0[4], al1[4], bl0[2], bl1[2];
                uint32_t ko = (kt - 8) * 32;
                ldsm4(ah0, bhm + ko);
                ldsm4(ah1, bhm + 16 * HPITCH + ko);
                ldsm4(al0, bhm + HLOFF + ko);
                ldsm4(al1, bhm + HLOFF + 16 * HPITCH + ko);
                ldsm2(bl0, baseBL + kt * 32);
                ldsm2(bl1, baseBL + 8 * BPITCH + kt * 32);
                mma_bf16(d[0][0], ah0, bh[kt][0]); mma_bf16(d[0][1], ah0, bh[kt][1]);
                mma_bf16(d[1][0], ah1, bh[kt][0]); mma_bf16(d[1][1], ah1, bh[kt][1]);
                mma_bf16(d[0][0], al0, bh[kt][0]); mma_bf16(d[0][1], al0, bh[kt][1]);
                mma_bf16(d[1][0], al1, bh[kt][0]); mma_bf16(d[1][1], al1, bh[kt][1]);
                mma_bf16(d[0][0], ah0, bl0); mma_bf16(d[0][1], ah0, bl1);
                mma_bf16(d[1][0], ah1, bl0); mma_bf16(d[1][1], ah1, bl1);
            }

            BAR_SYNC(1, NTHR);   // second half staged (+ x(s+1) ready)

            // ---- h-part MMAs, second half (kt 16..23) ----
            #pragma unroll
            for (int kt = 16; kt < 24; ++kt) {
                uint32_t ah0[4], ah1[4], al0[4], al1[4], bl0[2], bl1[2];
                uint32_t ko = (kt - 8) * 32;
                ldsm4(ah0, bhm + ko);
                ldsm4(ah1, bhm + 16 * HPITCH + ko);
                ldsm4(al0, bhm + HLOFF + ko);
                ldsm4(al1, bhm + HLOFF + 16 * HPITCH + ko);
                ldsm2(bl0, baseBL + kt * 32);
                ldsm2(bl1, baseBL + 8 * BPITCH + kt * 32);
                mma_bf16(d[0][0], ah0, bh[kt][0]); mma_bf16(d[0][1], ah0, bh[kt][1]);
                mma_bf16(d[1][0], ah1, bh[kt][0]); mma_bf16(d[1][1], ah1, bh[kt][1]);
                mma_bf16(d[0][0], al0, bh[kt][0]); mma_bf16(d[0][1], al0, bh[kt][1]);
                mma_bf16(d[1][0], al1, bh[kt][0]); mma_bf16(d[1][1], al1, bh[kt][1]);
                mma_bf16(d[0][0], ah0, bl0); mma_bf16(d[0][1], ah0, bl1);
                mma_bf16(d[1][0], ah1, bl0); mma_bf16(d[1][1], ah1, bl1);
            }

            // ---- in-register epilogue -> smem stage (bf16 hi/lo) ----
            #pragma unroll
            for (int mt = 0; mt < 2; ++mt)
                #pragma unroll
                for (int h2 = 0; h2 < 2; ++h2) {
                    float iv = d[mt][0][2 * h2 + 0];
                    float fv = d[mt][0][2 * h2 + 1];
                    float gv = d[mt][1][2 * h2 + 0];
                    float ov = d[mt][1][2 * h2 + 1];
                    int ci = 2 * mt + h2;
                    cst[ci] = sigf(fv) * cst[ci] + sigf(iv) * tanhx(gv);
                    float hn = sigf(ov) * tanhx(cst[ci]);
                    __nv_bfloat16 hb16 = __float2bfloat16(hn);
                    __nv_bfloat16 lb16 = __float2bfloat16(hn - __bfloat162float(hb16));
                    int r = 16 * mt + 8 * h2 + (lane >> 2);
                    *reinterpret_cast<__nv_bfloat16*>(
                        smem + HSTG + r * HSTG_PITCH + 2 * unit_l) = hb16;
                    *reinterpret_cast<__nv_bfloat16*>(
                        smem + HSTG + HSTG_LO + r * HSTG_PITCH + 2 * unit_l) = lb16;
                }

            BAR_SYNC(4, 256);    // compute-only: stage complete

            // ---- coalesced copy-out: 256 threads x one 16B chunk ----
            {
                int plane = tid >> 7;            // 0 hi, 1 lo
                int idx = tid & 127;
                int row = idx >> 2;
                int cpos = idx & 3;              // 4 chunks of 16B per row
                uint4 v = *reinterpret_cast<const uint4*>(
                    smem + HSTG + plane * HSTG_LO + row * HSTG_PITCH + cpos * 16);
                __nv_bfloat16* dst = plane
                    ? &g_hl[s & 1][g][row][slice * 32 + cpos * 8]
                    : &g_hh[s & 1][g][row][slice * 32 + cpos * 8];
                __stcg(reinterpret_cast<uint4*>(dst), v);
            }

            BAR_ARRIVE(2, NTHR);   // exchange warp publishes flag
        }
    }

    __syncthreads();   // exchange warp verified all final publishes

    // ---- final projection (slice 0, compute warps) ----
    if (slice == 0 && !is_x) {
        const int buf = (SEQ - 1) & 1;
        const float bo = b_out[0];
        for (int r4 = 0; r4 < 4; ++r4) {
            int r = wid * 4 + r4;
            int c0 = lane * 8;
            uint4 hv = __ldcg(reinterpret_cast<const uint4*>(&g_hh[buf][g][r][c0]));
            uint4 lv = __ldcg(reinterpret_cast<const uint4*>(&g_hl[buf][g][r][c0]));
            float acc = 0.0f;
            const uint32_t* hp = &hv.x;
            const uint32_t* lp = &lv.x;
            #pragma unroll
            for (int qq = 0; qq < 4; ++qq) {
                float2 h2 = __bfloat1622float2(*reinterpret_cast<const __nv_bfloat162*>(&hp[qq]));
                float2 l2 = __bfloat1622float2(*reinterpret_cast<const __nv_bfloat162*>(&lp[qq]));
                acc += (h2.x + l2.x) * W_out[c0 + 2 * qq]
                     + (h2.y + l2.y) * W_out[c0 + 2 * qq + 1];
            }
            #pragma unroll
            for (int off = 16; off > 0; off >>= 1)
                acc += __shfl_xor_sync(0xFFFFFFFFu, acc, off);
            if (lane == 0) out[g * MR + r] = acc + bo;
        }
    }
}

// ---------------------------------------------------------------------------
extern "C" void kernel_launch(void* const* d_in, const int* in_sizes, int n_in,
                              void* d_out, int out_size) {
    const float* x     = (const float*)d_in[0];
    const float* W_ih  = (const float*)d_in[1];
    const float* W_hh  = (const float*)d_in[2];
    const float* b_ih  = (const float*)d_in[3];
    const float* b_hh  = (const float*)d_in[4];
    const float* W_out = (const float*)d_in[5];
    const float* b_out = (const float*)d_in[6];
    float* out = (float*)d_out;

    prep_x<<<2048, 256>>>(x);
    cudaFuncSetAttribute(lstm_mma,
                         cudaFuncAttributeMaxDynamicSharedMemorySize, SMEM_BYTES);
    lstm_mma<<<NCTA, NTHR, SMEM_BYTES>>>(W_ih, W_hh, b_ih, b_hh,
                                         W_out, b_out, out);
}